// round 8
// baseline (speedup 1.0000x reference)
#include <cuda_runtime.h>
#include <cuda_bf16.h>
#include <cstdint>
#include <math.h>
#include <cub/block/block_radix_sort.cuh>

#define NQ 256
#define SSN 256
#define DD 256
#define HWT 16384
#define RTOT (NQ*SSN)

// ---------------- scratch (device globals; no allocation allowed) -----------
__device__ __align__(16) int   g_feat_idx[RTOT];
__device__ __align__(16) float g_keys[RTOT*DD];
__device__ __align__(16) float g_f[RTOT*DD];
__device__ __align__(16) float g_pf[RTOT*128];
__device__ __align__(16) float g_s1[RTOT*DD];
__device__ __align__(16) float g_qw[NQ*8*DD];
__device__ __align__(16) float g_g[NQ*8*DD];
__device__ __align__(16) float g_slotc[NQ*DD];

// ---------------- 1) per-row descending argsort + rank select ---------------
using Sorter = cub::BlockRadixSort<unsigned long long, 512, 32>;
struct SortSmem { union { Sorter::TempStorage ts; unsigned short sidx[HWT]; }; };

__global__ void __launch_bounds__(512, 1)
k_sort(const float* __restrict__ curio, const int* __restrict__ cov_sel)
{
    extern __shared__ char raw[];
    SortSmem& sm = *reinterpret_cast<SortSmem*>(raw);
    const int n = blockIdx.x;
    const float* row = curio + (size_t)n * HWT;
    unsigned long long k[32];
    const int base = threadIdx.x * 32;
#pragma unroll
    for (int j = 0; j < 32; ++j) {
        unsigned u = __float_as_uint(row[base + j]);
        unsigned mono = u ^ (((unsigned)((int)u >> 31)) | 0x80000000u);
        k[j] = ((unsigned long long)(~mono) << 14) | (unsigned)(base + j);
    }
    Sorter(sm.ts).Sort(k, 0, 46);
    __syncthreads();
#pragma unroll
    for (int j = 0; j < 32; ++j) sm.sidx[base + j] = (unsigned short)(k[j] & 0x3FFFu);
    __syncthreads();
    if (threadIdx.x < SSN) {
        int s = threadIdx.x;
        int rank = (s < 192) ? s : 192 + cov_sel[s - 192];
        g_feat_idx[n * SSN + s] = (int)sm.sidx[rank];
    }
}

// ---------------- 2) gather f and keys = f + p (warp per row) ---------------
__global__ void __launch_bounds__(256)
k_gather(const float* __restrict__ feat, const float* __restrict__ pos,
         const int* __restrict__ bidx)
{
    int w = threadIdx.x >> 5, l = threadIdx.x & 31;
    int r = blockIdx.x * 8 + w;
    int n = r >> 8;
    int i = g_feat_idx[r];
    int b = bidx[n];
    size_t src = ((size_t)i * 8 + b) * DD;
    size_t dst = (size_t)r * DD;
#pragma unroll
    for (int c = 0; c < 2; ++c) {
        int e = (l + c * 32) * 4;
        float4 fv = *(const float4*)(feat + src + e);
        float4 pv = *(const float4*)(pos + src + e);
        *(float4*)(g_f + dst + e) = fv;
        *(float4*)(g_keys + dst + e) =
            make_float4(fv.x + pv.x, fv.y + pv.y, fv.z + pv.z, fv.w + pv.w);
    }
}

// ---------------- 3) q, then qw = q@wk folded -------------------------------
__global__ void __launch_bounds__(256)
k_qprep(const float* __restrict__ slots, const float* __restrict__ ipw,
        const float* __restrict__ ipb)
{
    __shared__ float sl[DD], qs[DD];
    int n = blockIdx.x, t = threadIdx.x;
    sl[t] = slots[n * DD + t];
    __syncthreads();
    {
        const float* wr = ipw + (size_t)t * DD;
        float a = ipb[t];
#pragma unroll 8
        for (int e = 0; e < DD; e += 4) {
            float4 w4 = *(const float4*)(wr + e);
            a += w4.x*sl[e] + w4.y*sl[e+1] + w4.z*sl[e+2] + w4.w*sl[e+3];
        }
        qs[t] = a * 0.17677669529663687f;
    }
    __syncthreads();
    for (int h = 0; h < 8; ++h) {
        float a = 0.f;
#pragma unroll
        for (int d = 0; d < 32; ++d) {
            int hd = h * 32 + d;
            a += qs[hd] * __ldg(ipw + (size_t)(DD + hd) * DD + t);
        }
        g_qw[n * 2048 + h * DD + t] = a;
    }
}

// ---------------- 4) attention: logits->softmax->G --------------------------
#define ATTN_SMEM ((8*260 + 32*260 + 8*256)*4)
__global__ void __launch_bounds__(256)
k_attn()
{
    extern __shared__ float sm[];
    float* qw_s = sm;               // 8x260
    float* ks   = sm + 8*260;       // 32x260 (aliased as attn[256][8] later)
    float* lg   = sm + 8*260 + 32*260; // 8x256
    const int n = blockIdx.x, t = threadIdx.x;
    for (int i = t; i < 2048; i += 256)
        qw_s[(i >> 8)*260 + (i & 255)] = g_qw[n*2048 + i];
    __syncthreads();
    const int sl = t >> 3, h = t & 7;
    for (int sc = 0; sc < 8; ++sc) {
        for (int i = t; i < 32*64; i += 256) {
            int row = i >> 6, e4 = (i & 63)*4;
            *(float4*)(ks + row*260 + e4) =
                *(const float4*)(g_keys + ((size_t)(n*SSN + sc*32 + row))*DD + e4);
        }
        __syncthreads();
        float a = 0.f;
#pragma unroll 8
        for (int e = 0; e < DD; e += 4) {
            float4 kv = *(float4*)(ks + sl*260 + e);
            float4 qv = *(float4*)(qw_s + h*260 + e);
            a += kv.x*qv.x + kv.y*qv.y + kv.z*qv.z + kv.w*qv.w;
        }
        lg[h*SSN + sc*32 + sl] = a;
        __syncthreads();
    }
    float* at = ks;
    {
        int w = t >> 5, l = t & 31;
        float lv[8]; float mx = -1e30f;
#pragma unroll
        for (int k = 0; k < 8; ++k) { lv[k] = lg[w*SSN + l + k*32]; mx = fmaxf(mx, lv[k]); }
#pragma unroll
        for (int o = 16; o > 0; o >>= 1) mx = fmaxf(mx, __shfl_xor_sync(0xFFFFFFFFu, mx, o));
        float sum = 0.f;
#pragma unroll
        for (int k = 0; k < 8; ++k) { lv[k] = expf(lv[k] - mx); sum += lv[k]; }
#pragma unroll
        for (int o = 16; o > 0; o >>= 1) sum += __shfl_xor_sync(0xFFFFFFFFu, sum, o);
        float inv = 1.f / sum;
#pragma unroll
        for (int k = 0; k < 8; ++k) at[(l + k*32)*8 + w] = lv[k] * inv;
    }
    __syncthreads();
    float acc8[8] = {0,0,0,0,0,0,0,0};
    for (int s = 0; s < SSN; ++s) {
        float fv = g_f[((size_t)(n*SSN + s))*DD + t];
        const float* ap = at + s*8;
#pragma unroll
        for (int h2 = 0; h2 < 8; ++h2) acc8[h2] += ap[h2] * fv;
    }
#pragma unroll
    for (int h2 = 0; h2 < 8; ++h2) g_g[n*2048 + h2*DD + t] = acc8[h2];
}

// ---------------- 5) slot path: o, delta, LN, slot-MLP, slotc ---------------
__global__ void __launch_bounds__(256)
k_slotpath(const float* __restrict__ slots, const float* __restrict__ ipw,
           const float* __restrict__ ipb, const float* __restrict__ opw,
           const float* __restrict__ opb, const float* __restrict__ lng,
           const float* __restrict__ lnb, const float* __restrict__ sw1,
           const float* __restrict__ sb1, const float* __restrict__ sw2,
           const float* __restrict__ sb2, const float* __restrict__ gw1,
           const float* __restrict__ gb1, float* __restrict__ out)
{
    __shared__ float G[2048], ov[256], so[256], hid[128], ps[128], red[8];
    int n = blockIdx.x, t = threadIdx.x;
    for (int i = t; i < 2048; i += 256) G[i] = g_g[n*2048 + i];
    __syncthreads();
    {   // o = wv . G[h] + bv
        int h = t >> 5;
        const float* wr = ipw + (size_t)(512 + t) * DD;
        float a = ipb[512 + t];
#pragma unroll 8
        for (int e = 0; e < DD; e += 4) {
            float4 w4 = *(const float4*)(wr + e);
            a += w4.x*G[h*256+e] + w4.y*G[h*256+e+1] + w4.z*G[h*256+e+2] + w4.w*G[h*256+e+3];
        }
        ov[t] = a;
    }
    __syncthreads();
    float x;
    {   // delta + residual
        const float* wr = opw + (size_t)t * DD;
        float a = opb[t];
#pragma unroll 8
        for (int e = 0; e < DD; e += 4) {
            float4 w4 = *(const float4*)(wr + e);
            a += w4.x*ov[e] + w4.y*ov[e+1] + w4.z*ov[e+2] + w4.w*ov[e+3];
        }
        x = slots[n*DD + t] + a;
    }
    // layernorm
    float v = x;
#pragma unroll
    for (int o = 16; o > 0; o >>= 1) v += __shfl_xor_sync(0xFFFFFFFFu, v, o);
    if ((t & 31) == 0) red[t >> 5] = v;
    __syncthreads();
    float mu = 0.f;
#pragma unroll
    for (int i = 0; i < 8; ++i) mu += red[i];
    mu *= (1.f/256.f);
    __syncthreads();
    float d = x - mu; v = d * d;
#pragma unroll
    for (int o = 16; o > 0; o >>= 1) v += __shfl_xor_sync(0xFFFFFFFFu, v, o);
    if ((t & 31) == 0) red[t >> 5] = v;
    __syncthreads();
    float var = 0.f;
#pragma unroll
    for (int i = 0; i < 8; ++i) var += red[i];
    var *= (1.f/256.f);
    float sov = d * rsqrtf(var + 1e-5f) * lng[t] + lnb[t];
    so[t] = sov;
    out[n*DD + t] = sov;
    __syncthreads();
    if (t < 128) {
        const float* wr = sw1 + (size_t)t * DD;
        float a = sb1[t];
#pragma unroll 8
        for (int e = 0; e < DD; e += 4) {
            float4 w4 = *(const float4*)(wr + e);
            a += w4.x*so[e] + w4.y*so[e+1] + w4.z*so[e+2] + w4.w*so[e+3];
        }
        hid[t] = fmaxf(a, 0.f);
    }
    __syncthreads();
    if (t < 128) {
        const float* wr = sw2 + (size_t)t * 128;
        float a = sb2[t];
#pragma unroll 8
        for (int e = 0; e < 128; e += 4) {
            float4 w4 = *(const float4*)(wr + e);
            a += w4.x*hid[e] + w4.y*hid[e+1] + w4.z*hid[e+2] + w4.w*hid[e+3];
        }
        ps[t] = a;
    }
    __syncthreads();
    {   // slotc[n][j] = seg_b1[j] + sum_{i<128} ps[i]*seg_w1[j][i]
        const float* wr = gw1 + (size_t)t * DD;
        float a = gb1[t];
#pragma unroll 8
        for (int i = 0; i < 128; i += 4) {
            float4 w4 = *(const float4*)(wr + i);
            a += w4.x*ps[i] + w4.y*ps[i+1] + w4.z*ps[i+2] + w4.w*ps[i+3];
        }
        g_slotc[n*DD + t] = a;
    }
}

// ---------------- 6) feature MLP (fused two-layer GEMM, 128x128 tiles) ------
#define FM_SMEM ((128*129 + 128*33 + 128*33)*4)
__global__ void __launch_bounds__(256)
k_featmlp(const float* __restrict__ fw1, const float* __restrict__ fb1,
          const float* __restrict__ fw2, const float* __restrict__ fb2)
{
    extern __shared__ float smf[];
    float* H  = smf;                // 128x129
    float* As = smf + 128*129;      // 128x33
    float* Bs = As + 128*33;        // 128x33
    const int t = threadIdx.x;
    const int r0 = blockIdx.x * 128;
    const int ty = t >> 4, tx = t & 15;
    float acc[8][8];
#pragma unroll
    for (int i = 0; i < 8; ++i)
#pragma unroll
        for (int j = 0; j < 8; ++j) acc[i][j] = 0.f;
    for (int kc = 0; kc < 256; kc += 32) {
#pragma unroll
        for (int m = 0; m < 16; ++m) {
            int idx = m*256 + t; int row = idx >> 5, kk = idx & 31;
            As[row*33 + kk] = g_keys[(size_t)(r0 + row)*DD + kc + kk];
            Bs[row*33 + kk] = fw1[(size_t)row*DD + kc + kk];
        }
        __syncthreads();
#pragma unroll
        for (int k = 0; k < 32; ++k) {
            float a[8], b[8];
#pragma unroll
            for (int i = 0; i < 8; ++i) a[i] = As[(ty*8+i)*33 + k];
#pragma unroll
            for (int j = 0; j < 8; ++j) b[j] = Bs[(tx*8+j)*33 + k];
#pragma unroll
            for (int i = 0; i < 8; ++i)
#pragma unroll
                for (int j = 0; j < 8; ++j) acc[i][j] += a[i]*b[j];
        }
        __syncthreads();
    }
#pragma unroll
    for (int i = 0; i < 8; ++i)
#pragma unroll
        for (int j = 0; j < 8; ++j)
            H[(ty*8+i)*129 + tx*8+j] = fmaxf(acc[i][j] + __ldg(fb1 + tx*8+j), 0.f);
    __syncthreads();
#pragma unroll
    for (int i = 0; i < 8; ++i)
#pragma unroll
        for (int j = 0; j < 8; ++j) acc[i][j] = 0.f;
    for (int kc = 0; kc < 128; kc += 32) {
#pragma unroll
        for (int m = 0; m < 16; ++m) {
            int idx = m*256 + t; int row = idx >> 5, kk = idx & 31;
            Bs[row*33 + kk] = fw2[(size_t)row*128 + kc + kk];
        }
        __syncthreads();
#pragma unroll
        for (int k = 0; k < 32; ++k) {
            float a[8], b[8];
#pragma unroll
            for (int i = 0; i < 8; ++i) a[i] = H[(ty*8+i)*129 + kc + k];
#pragma unroll
            for (int j = 0; j < 8; ++j) b[j] = Bs[(tx*8+j)*33 + k];
#pragma unroll
            for (int i = 0; i < 8; ++i)
#pragma unroll
                for (int j = 0; j < 8; ++j) acc[i][j] += a[i]*b[j];
        }
        __syncthreads();
    }
#pragma unroll
    for (int i = 0; i < 8; ++i)
#pragma unroll
        for (int j = 0; j < 8; ++j)
            g_pf[(size_t)(r0 + ty*8+i)*128 + tx*8+j] = acc[i][j] + __ldg(fb2 + tx*8+j);
}

// ---------------- 7a) seg inner GEMM: relu(slotc + pf@w1f^T) ----------------
__global__ void __launch_bounds__(256)
k_seg1(const float* __restrict__ gw1)
{
    __shared__ float As[128*33], Bs[128*33], sc[128];
    const int t = threadIdx.x;
    const int r0 = blockIdx.x * 128;
    const int j0 = blockIdx.y * 128;
    const int n = r0 >> 8;
    if (t < 128) sc[t] = g_slotc[n*DD + j0 + t];
    const int ty = t >> 4, tx = t & 15;
    float acc[8][8];
#pragma unroll
    for (int i = 0; i < 8; ++i)
#pragma unroll
        for (int j = 0; j < 8; ++j) acc[i][j] = 0.f;
    for (int kc = 0; kc < 128; kc += 32) {
#pragma unroll
        for (int m = 0; m < 16; ++m) {
            int idx = m*256 + t; int row = idx >> 5, kk = idx & 31;
            As[row*33 + kk] = g_pf[(size_t)(r0 + row)*128 + kc + kk];
            Bs[row*33 + kk] = gw1[(size_t)(j0 + row)*DD + 128 + kc + kk];
        }
        __syncthreads();
#pragma unroll
        for (int k = 0; k < 32; ++k) {
            float a[8], b[8];
#pragma unroll
            for (int i = 0; i < 8; ++i) a[i] = As[(ty*8+i)*33 + k];
#pragma unroll
            for (int j = 0; j < 8; ++j) b[j] = Bs[(tx*8+j)*33 + k];
#pragma unroll
            for (int i = 0; i < 8; ++i)
#pragma unroll
                for (int j = 0; j < 8; ++j) acc[i][j] += a[i]*b[j];
        }
        __syncthreads();
    }
#pragma unroll
    for (int i = 0; i < 8; ++i)
#pragma unroll
        for (int j = 0; j < 8; ++j)
            g_s1[(size_t)(r0 + ty*8+i)*DD + j0 + tx*8+j] = fmaxf(acc[i][j] + sc[tx*8+j], 0.f);
}

// ---------------- 7b) seg head: 3-way GEMV + softmax + write + scatter ------
__global__ void __launch_bounds__(256)
k_seg2(const float* __restrict__ gw2, const float* __restrict__ gb2,
       float* __restrict__ out)
{
    int w = threadIdx.x >> 5, l = threadIdx.x & 31;
    int r = blockIdx.x * 8 + w;
    int n = r >> 8, s = r & 255;
    const float* inr = g_s1 + (size_t)r * DD;
    float a0 = 0.f, a1 = 0.f, a2 = 0.f;
#pragma unroll
    for (int k = l; k < DD; k += 32) {
        float x = inr[k];
        a0 += x * __ldg(gw2 + k);
        a1 += x * __ldg(gw2 + 256 + k);
        a2 += x * __ldg(gw2 + 512 + k);
    }
#pragma unroll
    for (int o = 16; o > 0; o >>= 1) {
        a0 += __shfl_xor_sync(0xFFFFFFFFu, a0, o);
        a1 += __shfl_xor_sync(0xFFFFFFFFu, a1, o);
        a2 += __shfl_xor_sync(0xFFFFFFFFu, a2, o);
    }
    if (l == 0) {
        a0 += gb2[0]; a1 += gb2[1]; a2 += gb2[2];
        float m = fmaxf(a0, fmaxf(a1, a2));
        float e0 = expf(a0 - m), e1 = expf(a1 - m), e2 = expf(a2 - m);
        float inv = 1.f / (e0 + e1 + e2);
        e0 *= inv; e1 *= inv; e2 *= inv;
        size_t pb = (size_t)65536 + 12582912 + ((size_t)s*256 + n)*3;
        out[pb] = e0; out[pb+1] = e1; out[pb+2] = e2;
        int i = g_feat_idx[r];
        size_t sb = (size_t)65536 + (size_t)n*49152 + i;
        out[sb] = e0; out[sb + 16384] = e1; out[sb + 32768] = e2;
    }
}

// ---------------------------------------------------------------------------
extern "C" void kernel_launch(void* const* d_in, const int* in_sizes, int n_in,
                              void* d_out, int out_size)
{
    const float* features = (const float*)d_in[0];
    const float* pos      = (const float*)d_in[1];
    const int*   bidx     = (const int*)d_in[2];
    const float* curio    = (const float*)d_in[3];
    const float* slots    = (const float*)d_in[5];
    const int*   cov_sel  = (const int*)d_in[6];
    const float* ipw = (const float*)d_in[7];
    const float* ipb = (const float*)d_in[8];
    const float* opw = (const float*)d_in[9];
    const float* opb = (const float*)d_in[10];
    const float* lng = (const float*)d_in[11];
    const float* lnb = (const float*)d_in[12];
    const float* sw1 = (const float*)d_in[13];
    const float* sb1 = (const float*)d_in[14];
    const float* sw2 = (const float*)d_in[15];
    const float* sb2 = (const float*)d_in[16];
    const float* fw1 = (const float*)d_in[17];
    const float* fb1 = (const float*)d_in[18];
    const float* fw2 = (const float*)d_in[19];
    const float* fb2 = (const float*)d_in[20];
    const float* gw1 = (const float*)d_in[21];
    const float* gb1 = (const float*)d_in[22];
    const float* gw2 = (const float*)d_in[23];
    const float* gb2 = (const float*)d_in[24];
    float* out = (float*)d_out;

    cudaFuncSetAttribute(k_sort, cudaFuncAttributeMaxDynamicSharedMemorySize,
                         (int)sizeof(SortSmem));
    cudaFuncSetAttribute(k_attn, cudaFuncAttributeMaxDynamicSharedMemorySize, ATTN_SMEM);
    cudaFuncSetAttribute(k_featmlp, cudaFuncAttributeMaxDynamicSharedMemorySize, FM_SMEM);

    cudaMemsetAsync(d_out, 0, (size_t)out_size * sizeof(float));
    k_sort<<<NQ, 512, sizeof(SortSmem)>>>(curio, cov_sel);
    k_gather<<<RTOT/8, 256>>>(features, pos, bidx);
    k_qprep<<<NQ, 256>>>(slots, ipw, ipb);
    k_attn<<<NQ, 256, ATTN_SMEM>>>();
    k_slotpath<<<NQ, 256>>>(slots, ipw, ipb, opw, opb, lng, lnb,
                            sw1, sb1, sw2, sb2, gw1, gb1, out);
    k_featmlp<<<RTOT/128, 256, FM_SMEM>>>(fw1, fb1, fw2, fb2);
    dim3 gs(RTOT/128, 2);
    k_seg1<<<gs, 256>>>(gw1);
    k_seg2<<<RTOT/8, 256>>>(gw2, gb2, out);
}

// round 9
// speedup vs baseline: 1.0253x; 1.0253x over previous
#include <cuda_runtime.h>
#include <cuda_bf16.h>
#include <cstdint>
#include <math.h>
#include <cub/block/block_radix_sort.cuh>

#define NQ 256
#define SSN 256
#define DD 256
#define HWT 16384
#define RTOT (NQ*SSN)

typedef unsigned long long ull;

// ---------------- scratch (device globals; no allocation allowed) -----------
__device__ __align__(16) int   g_feat_idx[RTOT];
__device__ __align__(16) float g_keys[RTOT*DD];
__device__ __align__(16) float g_f[RTOT*DD];
__device__ __align__(16) float g_pf[RTOT*128];
__device__ __align__(16) float g_s1[RTOT*DD];
__device__ __align__(16) float g_qw[NQ*8*DD];
__device__ __align__(16) float g_gp[2][NQ*8*DD];
__device__ __align__(16) float g_slotc[NQ*DD];
__device__ __align__(16) float g_lg[NQ*8*SSN];
__device__ __align__(16) float g_at[NQ*SSN*8];

// ---------------- f32x2 packed FMA helpers ----------------------------------
__device__ __forceinline__ ull pk2(float x, float y) {
    ull r; asm("mov.b64 %0, {%1, %2};" : "=l"(r) : "f"(x), "f"(y)); return r;
}
__device__ __forceinline__ void fma2(ull& d, ull a, ull b) {
    asm("fma.rn.f32x2 %0, %1, %2, %0;" : "+l"(d) : "l"(a), "l"(b));
}
__device__ __forceinline__ float2 upk2(ull v) {
    float2 f; asm("mov.b64 {%0, %1}, %2;" : "=f"(f.x), "=f"(f.y) : "l"(v)); return f;
}

// ---------------- 1) per-row descending argsort + rank select ---------------
// key = (~mono(value) << 14) | idx. Initial blocked order is idx-ascending and
// radix ranking is stable, so sorting only bits [14,46) yields identical
// results to the full 46-bit sort (ties stay idx-ascending = jnp stable sort).
using Sorter = cub::BlockRadixSort<unsigned long long, 512, 32>;
struct SortSmem { union { Sorter::TempStorage ts; unsigned short sidx[HWT]; }; };

__global__ void __launch_bounds__(512, 1)
k_sort(const float* __restrict__ curio, const int* __restrict__ cov_sel)
{
    extern __shared__ char raw[];
    SortSmem& sm = *reinterpret_cast<SortSmem*>(raw);
    const int n = blockIdx.x;
    const float* row = curio + (size_t)n * HWT;
    unsigned long long k[32];
    const int base = threadIdx.x * 32;
#pragma unroll
    for (int j = 0; j < 32; ++j) {
        unsigned u = __float_as_uint(row[base + j]);
        unsigned mono = u ^ (((unsigned)((int)u >> 31)) | 0x80000000u);
        k[j] = ((unsigned long long)(~mono) << 14) | (unsigned)(base + j);
    }
    Sorter(sm.ts).Sort(k, 14, 46);
    __syncthreads();
#pragma unroll
    for (int j = 0; j < 32; ++j) sm.sidx[base + j] = (unsigned short)(k[j] & 0x3FFFu);
    __syncthreads();
    if (threadIdx.x < SSN) {
        int s = threadIdx.x;
        int rank = (s < 192) ? s : 192 + cov_sel[s - 192];
        g_feat_idx[n * SSN + s] = (int)sm.sidx[rank];
    }
}

// ---------------- 2) gather f and keys = f + p (warp per row) ---------------
__global__ void __launch_bounds__(256)
k_gather(const float* __restrict__ feat, const float* __restrict__ pos,
         const int* __restrict__ bidx)
{
    int w = threadIdx.x >> 5, l = threadIdx.x & 31;
    int r = blockIdx.x * 8 + w;
    int n = r >> 8;
    int i = g_feat_idx[r];
    int b = bidx[n];
    size_t src = ((size_t)i * 8 + b) * DD;
    size_t dst = (size_t)r * DD;
#pragma unroll
    for (int c = 0; c < 2; ++c) {
        int e = (l + c * 32) * 4;
        float4 fv = *(const float4*)(feat + src + e);
        float4 pv = *(const float4*)(pos + src + e);
        *(float4*)(g_f + dst + e) = fv;
        *(float4*)(g_keys + dst + e) =
            make_float4(fv.x + pv.x, fv.y + pv.y, fv.z + pv.z, fv.w + pv.w);
    }
}

// ---------------- 3) q, then qw = q@wk folded -------------------------------
__global__ void __launch_bounds__(256)
k_qprep(const float* __restrict__ slots, const float* __restrict__ ipw,
        const float* __restrict__ ipb)
{
    __shared__ float sl[DD], qs[DD];
    int n = blockIdx.x, t = threadIdx.x;
    sl[t] = slots[n * DD + t];
    __syncthreads();
    {
        const float* wr = ipw + (size_t)t * DD;
        float a = ipb[t];
#pragma unroll 8
        for (int e = 0; e < DD; e += 4) {
            float4 w4 = *(const float4*)(wr + e);
            a += w4.x*sl[e] + w4.y*sl[e+1] + w4.z*sl[e+2] + w4.w*sl[e+3];
        }
        qs[t] = a * 0.17677669529663687f;
    }
    __syncthreads();
    for (int h = 0; h < 8; ++h) {
        float a = 0.f;
#pragma unroll
        for (int d = 0; d < 32; ++d) {
            int hd = h * 32 + d;
            a += qs[hd] * __ldg(ipw + (size_t)(DD + hd) * DD + t);
        }
        g_qw[n * 2048 + h * DD + t] = a;
    }
}

// ---------------- 4a) logits: grid (NQ, 4), 64 s-rows per block -------------
#define LG_SMEM ((8*260 + 32*260)*4)
__global__ void __launch_bounds__(256)
k_logits()
{
    extern __shared__ float sm[];
    float* qw_s = sm;             // 8x260
    float* ks   = sm + 8*260;     // 32x260
    const int n = blockIdx.x, q = blockIdx.y, t = threadIdx.x;
    for (int i = t; i < 2048; i += 256)
        qw_s[(i >> 8)*260 + (i & 255)] = g_qw[n*2048 + i];
    const int sl = t >> 3, h = t & 7;
#pragma unroll
    for (int c = 0; c < 2; ++c) {
        int s0 = q*64 + c*32;
        __syncthreads();
        for (int i = t; i < 32*64; i += 256) {
            int row = i >> 6, e4 = (i & 63)*4;
            *(float4*)(ks + row*260 + e4) =
                *(const float4*)(g_keys + ((size_t)(n*SSN + s0 + row))*DD + e4);
        }
        __syncthreads();
        float a = 0.f;
#pragma unroll 8
        for (int e = 0; e < DD; e += 4) {
            float4 kv = *(float4*)(ks + sl*260 + e);
            float4 qv = *(float4*)(qw_s + h*260 + e);
            a += kv.x*qv.x + kv.y*qv.y + kv.z*qv.z + kv.w*qv.w;
        }
        g_lg[n*2048 + h*SSN + s0 + sl] = a;
    }
}

// ---------------- 4b) softmax over s per (n,h) ------------------------------
__global__ void __launch_bounds__(256)
k_soft()
{
    int n = blockIdx.x, t = threadIdx.x, w = t >> 5, l = t & 31;
    float lv[8]; float mx = -1e30f;
#pragma unroll
    for (int k = 0; k < 8; ++k) {
        lv[k] = g_lg[n*2048 + w*SSN + l + k*32];
        mx = fmaxf(mx, lv[k]);
    }
#pragma unroll
    for (int o = 16; o > 0; o >>= 1) mx = fmaxf(mx, __shfl_xor_sync(0xFFFFFFFFu, mx, o));
    float sum = 0.f;
#pragma unroll
    for (int k = 0; k < 8; ++k) { lv[k] = expf(lv[k] - mx); sum += lv[k]; }
#pragma unroll
    for (int o = 16; o > 0; o >>= 1) sum += __shfl_xor_sync(0xFFFFFFFFu, sum, o);
    float inv = 1.f / sum;
#pragma unroll
    for (int k = 0; k < 8; ++k) g_at[n*2048 + (l + k*32)*8 + w] = lv[k] * inv;
}

// ---------------- 4c) G partial sums: grid (NQ, 2) --------------------------
__global__ void __launch_bounds__(256)
k_g()
{
    __shared__ float at[128*8];
    int n = blockIdx.x, half = blockIdx.y, t = threadIdx.x;
    for (int i = t; i < 1024; i += 256) at[i] = g_at[n*2048 + half*1024 + i];
    __syncthreads();
    float acc[8] = {0,0,0,0,0,0,0,0};
    int base = n*SSN + half*128;
#pragma unroll 4
    for (int s = 0; s < 128; ++s) {
        float fv = g_f[((size_t)(base + s))*DD + t];
#pragma unroll
        for (int h = 0; h < 8; ++h) acc[h] += at[s*8 + h] * fv;
    }
#pragma unroll
    for (int h = 0; h < 8; ++h) g_gp[half][n*2048 + h*DD + t] = acc[h];
}

// ---------------- 5) slot path: o, delta, LN, slot-MLP, slotc ---------------
__global__ void __launch_bounds__(256)
k_slotpath(const float* __restrict__ slots, const float* __restrict__ ipw,
           const float* __restrict__ ipb, const float* __restrict__ opw,
           const float* __restrict__ opb, const float* __restrict__ lng,
           const float* __restrict__ lnb, const float* __restrict__ sw1,
           const float* __restrict__ sb1, const float* __restrict__ sw2,
           const float* __restrict__ sb2, const float* __restrict__ gw1,
           const float* __restrict__ gb1, float* __restrict__ out)
{
    __shared__ float G[2048], ov[256], so[256], hid[128], ps[128], red[8];
    int n = blockIdx.x, t = threadIdx.x;
    for (int i = t; i < 2048; i += 256)
        G[i] = g_gp[0][n*2048 + i] + g_gp[1][n*2048 + i];
    __syncthreads();
    {
        int h = t >> 5;
        const float* wr = ipw + (size_t)(512 + t) * DD;
        float a = ipb[512 + t];
#pragma unroll 8
        for (int e = 0; e < DD; e += 4) {
            float4 w4 = *(const float4*)(wr + e);
            a += w4.x*G[h*256+e] + w4.y*G[h*256+e+1] + w4.z*G[h*256+e+2] + w4.w*G[h*256+e+3];
        }
        ov[t] = a;
    }
    __syncthreads();
    float x;
    {
        const float* wr = opw + (size_t)t * DD;
        float a = opb[t];
#pragma unroll 8
        for (int e = 0; e < DD; e += 4) {
            float4 w4 = *(const float4*)(wr + e);
            a += w4.x*ov[e] + w4.y*ov[e+1] + w4.z*ov[e+2] + w4.w*ov[e+3];
        }
        x = slots[n*DD + t] + a;
    }
    float v = x;
#pragma unroll
    for (int o = 16; o > 0; o >>= 1) v += __shfl_xor_sync(0xFFFFFFFFu, v, o);
    if ((t & 31) == 0) red[t >> 5] = v;
    __syncthreads();
    float mu = 0.f;
#pragma unroll
    for (int i = 0; i < 8; ++i) mu += red[i];
    mu *= (1.f/256.f);
    __syncthreads();
    float d = x - mu; v = d * d;
#pragma unroll
    for (int o = 16; o > 0; o >>= 1) v += __shfl_xor_sync(0xFFFFFFFFu, v, o);
    if ((t & 31) == 0) red[t >> 5] = v;
    __syncthreads();
    float var = 0.f;
#pragma unroll
    for (int i = 0; i < 8; ++i) var += red[i];
    var *= (1.f/256.f);
    float sov = d * rsqrtf(var + 1e-5f) * lng[t] + lnb[t];
    so[t] = sov;
    out[n*DD + t] = sov;
    __syncthreads();
    if (t < 128) {
        const float* wr = sw1 + (size_t)t * DD;
        float a = sb1[t];
#pragma unroll 8
        for (int e = 0; e < DD; e += 4) {
            float4 w4 = *(const float4*)(wr + e);
            a += w4.x*so[e] + w4.y*so[e+1] + w4.z*so[e+2] + w4.w*so[e+3];
        }
        hid[t] = fmaxf(a, 0.f);
    }
    __syncthreads();
    if (t < 128) {
        const float* wr = sw2 + (size_t)t * 128;
        float a = sb2[t];
#pragma unroll 8
        for (int e = 0; e < 128; e += 4) {
            float4 w4 = *(const float4*)(wr + e);
            a += w4.x*hid[e] + w4.y*hid[e+1] + w4.z*hid[e+2] + w4.w*hid[e+3];
        }
        ps[t] = a;
    }
    __syncthreads();
    {
        const float* wr = gw1 + (size_t)t * DD;
        float a = gb1[t];
#pragma unroll 8
        for (int i = 0; i < 128; i += 4) {
            float4 w4 = *(const float4*)(wr + i);
            a += w4.x*ps[i] + w4.y*ps[i+1] + w4.z*ps[i+2] + w4.w*ps[i+3];
        }
        g_slotc[n*DD + t] = a;
    }
}

// ---------------- 6) feature MLP (fused two-layer GEMM, f32x2) --------------
#define FM_SMEM ((128*129 + 128*33 + 128*33)*4)
__global__ void __launch_bounds__(256)
k_featmlp(const float* __restrict__ fw1, const float* __restrict__ fb1,
          const float* __restrict__ fw2, const float* __restrict__ fb2)
{
    extern __shared__ float smf[];
    float* H  = smf;
    float* As = smf + 128*129;
    float* Bs = As + 128*33;
    const int t = threadIdx.x;
    const int r0 = blockIdx.x * 128;
    const int ty = t >> 4, tx = t & 15;
    ull acc[8][4];
#pragma unroll
    for (int i = 0; i < 8; ++i)
#pragma unroll
        for (int j = 0; j < 4; ++j) acc[i][j] = 0ull;
    for (int kc = 0; kc < 256; kc += 32) {
#pragma unroll
        for (int m = 0; m < 16; ++m) {
            int idx = m*256 + t; int row = idx >> 5, kk = idx & 31;
            As[row*33 + kk] = g_keys[(size_t)(r0 + row)*DD + kc + kk];
            Bs[row*33 + kk] = fw1[(size_t)row*DD + kc + kk];
        }
        __syncthreads();
#pragma unroll
        for (int k = 0; k < 32; ++k) {
            float a[8], b[8];
#pragma unroll
            for (int i = 0; i < 8; ++i) a[i] = As[(ty*8+i)*33 + k];
#pragma unroll
            for (int j = 0; j < 8; ++j) b[j] = Bs[(tx*8+j)*33 + k];
            ull bd[4];
#pragma unroll
            for (int j = 0; j < 4; ++j) bd[j] = pk2(b[2*j], b[2*j+1]);
#pragma unroll
            for (int i = 0; i < 8; ++i) {
                ull ad = pk2(a[i], a[i]);
#pragma unroll
                for (int j = 0; j < 4; ++j) fma2(acc[i][j], ad, bd[j]);
            }
        }
        __syncthreads();
    }
#pragma unroll
    for (int i = 0; i < 8; ++i)
#pragma unroll
        for (int j = 0; j < 4; ++j) {
            float2 f2 = upk2(acc[i][j]);
            H[(ty*8+i)*129 + tx*8 + 2*j]   = fmaxf(f2.x + __ldg(fb1 + tx*8 + 2*j),   0.f);
            H[(ty*8+i)*129 + tx*8 + 2*j+1] = fmaxf(f2.y + __ldg(fb1 + tx*8 + 2*j+1), 0.f);
            acc[i][j] = 0ull;
        }
    __syncthreads();
    for (int kc = 0; kc < 128; kc += 32) {
#pragma unroll
        for (int m = 0; m < 16; ++m) {
            int idx = m*256 + t; int row = idx >> 5, kk = idx & 31;
            Bs[row*33 + kk] = fw2[(size_t)row*128 + kc + kk];
        }
        __syncthreads();
#pragma unroll
        for (int k = 0; k < 32; ++k) {
            float a[8], b[8];
#pragma unroll
            for (int i = 0; i < 8; ++i) a[i] = H[(ty*8+i)*129 + kc + k];
#pragma unroll
            for (int j = 0; j < 8; ++j) b[j] = Bs[(tx*8+j)*33 + k];
            ull bd[4];
#pragma unroll
            for (int j = 0; j < 4; ++j) bd[j] = pk2(b[2*j], b[2*j+1]);
#pragma unroll
            for (int i = 0; i < 8; ++i) {
                ull ad = pk2(a[i], a[i]);
#pragma unroll
                for (int j = 0; j < 4; ++j) fma2(acc[i][j], ad, bd[j]);
            }
        }
        __syncthreads();
    }
#pragma unroll
    for (int i = 0; i < 8; ++i)
#pragma unroll
        for (int j = 0; j < 4; ++j) {
            float2 f2 = upk2(acc[i][j]);
            g_pf[(size_t)(r0 + ty*8+i)*128 + tx*8 + 2*j]   = f2.x + __ldg(fb2 + tx*8 + 2*j);
            g_pf[(size_t)(r0 + ty*8+i)*128 + tx*8 + 2*j+1] = f2.y + __ldg(fb2 + tx*8 + 2*j+1);
        }
}

// ---------------- 7a) seg inner GEMM: relu(slotc + pf@w1f^T), f32x2 ---------
__global__ void __launch_bounds__(256)
k_seg1(const float* __restrict__ gw1)
{
    __shared__ float As[128*33], Bs[128*33], sc[128];
    const int t = threadIdx.x;
    const int r0 = blockIdx.x * 128;
    const int j0 = blockIdx.y * 128;
    const int n = r0 >> 8;
    if (t < 128) sc[t] = g_slotc[n*DD + j0 + t];
    const int ty = t >> 4, tx = t & 15;
    ull acc[8][4];
#pragma unroll
    for (int i = 0; i < 8; ++i)
#pragma unroll
        for (int j = 0; j < 4; ++j) acc[i][j] = 0ull;
    for (int kc = 0; kc < 128; kc += 32) {
#pragma unroll
        for (int m = 0; m < 16; ++m) {
            int idx = m*256 + t; int row = idx >> 5, kk = idx & 31;
            As[row*33 + kk] = g_pf[(size_t)(r0 + row)*128 + kc + kk];
            Bs[row*33 + kk] = gw1[(size_t)(j0 + row)*DD + 128 + kc + kk];
        }
        __syncthreads();
#pragma unroll
        for (int k = 0; k < 32; ++k) {
            float a[8], b[8];
#pragma unroll
            for (int i = 0; i < 8; ++i) a[i] = As[(ty*8+i)*33 + k];
#pragma unroll
            for (int j = 0; j < 8; ++j) b[j] = Bs[(tx*8+j)*33 + k];
            ull bd[4];
#pragma unroll
            for (int j = 0; j < 4; ++j) bd[j] = pk2(b[2*j], b[2*j+1]);
#pragma unroll
            for (int i = 0; i < 8; ++i) {
                ull ad = pk2(a[i], a[i]);
#pragma unroll
                for (int j = 0; j < 4; ++j) fma2(acc[i][j], ad, bd[j]);
            }
        }
        __syncthreads();
    }
#pragma unroll
    for (int i = 0; i < 8; ++i)
#pragma unroll
        for (int j = 0; j < 4; ++j) {
            float2 f2 = upk2(acc[i][j]);
            g_s1[(size_t)(r0 + ty*8+i)*DD + j0 + tx*8 + 2*j]   = fmaxf(f2.x + sc[tx*8 + 2*j],   0.f);
            g_s1[(size_t)(r0 + ty*8+i)*DD + j0 + tx*8 + 2*j+1] = fmaxf(f2.y + sc[tx*8 + 2*j+1], 0.f);
        }
}

// ---------------- 7b) seg head: 3-way GEMV + softmax + write + scatter ------
__global__ void __launch_bounds__(256)
k_seg2(const float* __restrict__ gw2, const float* __restrict__ gb2,
       float* __restrict__ out)
{
    int w = threadIdx.x >> 5, l = threadIdx.x & 31;
    int r = blockIdx.x * 8 + w;
    int n = r >> 8, s = r & 255;
    const float* inr = g_s1 + (size_t)r * DD;
    float a0 = 0.f, a1 = 0.f, a2 = 0.f;
#pragma unroll
    for (int k = l; k < DD; k += 32) {
        float x = inr[k];
        a0 += x * __ldg(gw2 + k);
        a1 += x * __ldg(gw2 + 256 + k);
        a2 += x * __ldg(gw2 + 512 + k);
    }
#pragma unroll
    for (int o = 16; o > 0; o >>= 1) {
        a0 += __shfl_xor_sync(0xFFFFFFFFu, a0, o);
        a1 += __shfl_xor_sync(0xFFFFFFFFu, a1, o);
        a2 += __shfl_xor_sync(0xFFFFFFFFu, a2, o);
    }
    if (l == 0) {
        a0 += gb2[0]; a1 += gb2[1]; a2 += gb2[2];
        float m = fmaxf(a0, fmaxf(a1, a2));
        float e0 = expf(a0 - m), e1 = expf(a1 - m), e2 = expf(a2 - m);
        float inv = 1.f / (e0 + e1 + e2);
        e0 *= inv; e1 *= inv; e2 *= inv;
        size_t pb = (size_t)65536 + 12582912 + ((size_t)s*256 + n)*3;
        out[pb] = e0; out[pb+1] = e1; out[pb+2] = e2;
        int i = g_feat_idx[r];
        size_t sb = (size_t)65536 + (size_t)n*49152 + i;
        out[sb] = e0; out[sb + 16384] = e1; out[sb + 32768] = e2;
    }
}

// ---------------------------------------------------------------------------
extern "C" void kernel_launch(void* const* d_in, const int* in_sizes, int n_in,
                              void* d_out, int out_size)
{
    const float* features = (const float*)d_in[0];
    const float* pos      = (const float*)d_in[1];
    const int*   bidx     = (const int*)d_in[2];
    const float* curio    = (const float*)d_in[3];
    const float* slots    = (const float*)d_in[5];
    const int*   cov_sel  = (const int*)d_in[6];
    const float* ipw = (const float*)d_in[7];
    const float* ipb = (const float*)d_in[8];
    const float* opw = (const float*)d_in[9];
    const float* opb = (const float*)d_in[10];
    const float* lng = (const float*)d_in[11];
    const float* lnb = (const float*)d_in[12];
    const float* sw1 = (const float*)d_in[13];
    const float* sb1 = (const float*)d_in[14];
    const float* sw2 = (const float*)d_in[15];
    const float* sb2 = (const float*)d_in[16];
    const float* fw1 = (const float*)d_in[17];
    const float* fb1 = (const float*)d_in[18];
    const float* fw2 = (const float*)d_in[19];
    const float* fb2 = (const float*)d_in[20];
    const float* gw1 = (const float*)d_in[21];
    const float* gb1 = (const float*)d_in[22];
    const float* gw2 = (const float*)d_in[23];
    const float* gb2 = (const float*)d_in[24];
    float* out = (float*)d_out;

    cudaFuncSetAttribute(k_sort, cudaFuncAttributeMaxDynamicSharedMemorySize,
                         (int)sizeof(SortSmem));
    cudaFuncSetAttribute(k_featmlp, cudaFuncAttributeMaxDynamicSharedMemorySize, FM_SMEM);

    cudaMemsetAsync(d_out, 0, (size_t)out_size * sizeof(float));
    k_sort<<<NQ, 512, sizeof(SortSmem)>>>(curio, cov_sel);
    k_gather<<<RTOT/8, 256>>>(features, pos, bidx);
    k_qprep<<<NQ, 256>>>(slots, ipw, ipb);
    dim3 glog(NQ, 4);
    k_logits<<<glog, 256, LG_SMEM>>>();
    k_soft<<<NQ, 256>>>();
    dim3 gg(NQ, 2);
    k_g<<<gg, 256>>>();
    k_slotpath<<<NQ, 256>>>(slots, ipw, ipb, opw, opb, lng, lnb,
                            sw1, sb1, sw2, sb2, gw1, gb1, out);
    k_featmlp<<<RTOT/128, 256, FM_SMEM>>>(fw1, fb1, fw2, fb2);
    dim3 gs(RTOT/128, 2);
    k_seg1<<<gs, 256>>>(gw1);
    k_seg2<<<RTOT/8, 256>>>(gw2, gb2, out);
}

// round 10
// speedup vs baseline: 1.5032x; 1.4661x over previous
#include <cuda_runtime.h>
#include <cuda_bf16.h>
#include <cstdint>
#include <math.h>
#include <cub/block/block_radix_sort.cuh>

#define NQ 256
#define SSN 256
#define DD 256
#define HWT 16384
#define RTOT (NQ*SSN)

// ---------------- scratch (device globals; no allocation allowed) -----------
__device__ __align__(16) int   g_feat_idx[RTOT];
__device__ __align__(16) float g_keys[RTOT*DD];
__device__ __align__(16) float g_f[RTOT*DD];
__device__ __align__(16) float g_s1[RTOT*DD];
__device__ __align__(16) float g_qw[NQ*8*DD];
__device__ __align__(16) float g_gp[2][NQ*8*DD];
__device__ __align__(16) float g_slotc[NQ*DD];
__device__ __align__(16) float g_lg[NQ*8*SSN];
__device__ __align__(16) float g_at[NQ*SSN*8];

// ---------------- tf32 mma helpers ------------------------------------------
__device__ __forceinline__ unsigned rna(float x) {
    unsigned o; asm("cvt.rna.tf32.f32 %0, %1;" : "=r"(o) : "f"(x)); return o;
}
__device__ __forceinline__ void mma_tf32(float* c, const unsigned* a, const unsigned* b) {
    asm volatile("mma.sync.aligned.m16n8k8.row.col.f32.tf32.tf32.f32 "
        "{%0,%1,%2,%3}, {%4,%5,%6,%7}, {%8,%9}, {%0,%1,%2,%3};"
        : "+f"(c[0]), "+f"(c[1]), "+f"(c[2]), "+f"(c[3])
        : "r"(a[0]), "r"(a[1]), "r"(a[2]), "r"(a[3]), "r"(b[0]), "r"(b[1]));
}

// ---------------- profiling alignment dummies --------------------------------
__global__ void k_nop() {}

// ---------------- 1) per-row stable descending argsort + rank select --------
// Stable radix SortDescending on mono(float) keys with u16 idx payload:
// ties keep input (idx-ascending) order == jnp.argsort(-x) exactly.
using Sorter = cub::BlockRadixSort<unsigned, 512, 32, unsigned short>;
struct SortSmem { union { Sorter::TempStorage ts; unsigned short sidx[HWT]; }; };

__global__ void __launch_bounds__(512, 1)
k_sort(const float* __restrict__ curio, const int* __restrict__ cov_sel)
{
    extern __shared__ char raw[];
    SortSmem& sm = *reinterpret_cast<SortSmem*>(raw);
    const int n = blockIdx.x;
    const float* row = curio + (size_t)n * HWT;
    unsigned k[32]; unsigned short v[32];
    const int base = threadIdx.x * 32;
#pragma unroll
    for (int j = 0; j < 32; ++j) {
        unsigned u = __float_as_uint(row[base + j]);
        k[j] = u ^ (((unsigned)((int)u >> 31)) | 0x80000000u);
        v[j] = (unsigned short)(base + j);
    }
    Sorter(sm.ts).SortDescending(k, v, 0, 32);
    __syncthreads();
#pragma unroll
    for (int j = 0; j < 32; ++j) sm.sidx[base + j] = v[j];
    __syncthreads();
    if (threadIdx.x < SSN) {
        int s = threadIdx.x;
        int rank = (s < 192) ? s : 192 + cov_sel[s - 192];
        g_feat_idx[n * SSN + s] = (int)sm.sidx[rank];
    }
}

// ---------------- 2) gather f and keys = f + p (warp per row) ---------------
__global__ void __launch_bounds__(256)
k_gather(const float* __restrict__ feat, const float* __restrict__ pos,
         const int* __restrict__ bidx)
{
    int w = threadIdx.x >> 5, l = threadIdx.x & 31;
    int r = blockIdx.x * 8 + w;
    int n = r >> 8;
    int i = g_feat_idx[r];
    int b = bidx[n];
    size_t src = ((size_t)i * 8 + b) * DD;
    size_t dst = (size_t)r * DD;
#pragma unroll
    for (int c = 0; c < 2; ++c) {
        int e = (l + c * 32) * 4;
        float4 fv = *(const float4*)(feat + src + e);
        float4 pv = *(const float4*)(pos + src + e);
        *(float4*)(g_f + dst + e) = fv;
        *(float4*)(g_keys + dst + e) =
            make_float4(fv.x + pv.x, fv.y + pv.y, fv.z + pv.z, fv.w + pv.w);
    }
}

// ---------------- 3) q, then qw = q@wk folded -------------------------------
__global__ void __launch_bounds__(256)
k_qprep(const float* __restrict__ slots, const float* __restrict__ ipw,
        const float* __restrict__ ipb)
{
    __shared__ float sl[DD], qs[DD];
    int n = blockIdx.x, t = threadIdx.x;
    sl[t] = slots[n * DD + t];
    __syncthreads();
    {
        const float* wr = ipw + (size_t)t * DD;
        float a = ipb[t];
#pragma unroll 8
        for (int e = 0; e < DD; e += 4) {
            float4 w4 = *(const float4*)(wr + e);
            a += w4.x*sl[e] + w4.y*sl[e+1] + w4.z*sl[e+2] + w4.w*sl[e+3];
        }
        qs[t] = a * 0.17677669529663687f;
    }
    __syncthreads();
    for (int h = 0; h < 8; ++h) {
        float a = 0.f;
#pragma unroll
        for (int d = 0; d < 32; ++d) {
            int hd = h * 32 + d;
            a += qs[hd] * __ldg(ipw + (size_t)(DD + hd) * DD + t);
        }
        g_qw[n * 2048 + h * DD + t] = a;
    }
}

// ---------------- 4a) logits: grid (NQ, 4) ----------------------------------
#define LG_SMEM ((8*260 + 32*260)*4)
__global__ void __launch_bounds__(256)
k_logits()
{
    extern __shared__ float sm[];
    float* qw_s = sm;
    float* ks   = sm + 8*260;
    const int n = blockIdx.x, q = blockIdx.y, t = threadIdx.x;
    for (int i = t; i < 2048; i += 256)
        qw_s[(i >> 8)*260 + (i & 255)] = g_qw[n*2048 + i];
    const int sl = t >> 3, h = t & 7;
#pragma unroll
    for (int c = 0; c < 2; ++c) {
        int s0 = q*64 + c*32;
        __syncthreads();
        for (int i = t; i < 32*64; i += 256) {
            int row = i >> 6, e4 = (i & 63)*4;
            *(float4*)(ks + row*260 + e4) =
                *(const float4*)(g_keys + ((size_t)(n*SSN + s0 + row))*DD + e4);
        }
        __syncthreads();
        float a = 0.f;
#pragma unroll 8
        for (int e = 0; e < DD; e += 4) {
            float4 kv = *(float4*)(ks + sl*260 + e);
            float4 qv = *(float4*)(qw_s + h*260 + e);
            a += kv.x*qv.x + kv.y*qv.y + kv.z*qv.z + kv.w*qv.w;
        }
        g_lg[n*2048 + h*SSN + s0 + sl] = a;
    }
}

// ---------------- 4b) softmax over s per (n,h) ------------------------------
__global__ void __launch_bounds__(256)
k_soft()
{
    int n = blockIdx.x, t = threadIdx.x, w = t >> 5, l = t & 31;
    float lv[8]; float mx = -1e30f;
#pragma unroll
    for (int k = 0; k < 8; ++k) {
        lv[k] = g_lg[n*2048 + w*SSN + l + k*32];
        mx = fmaxf(mx, lv[k]);
    }
#pragma unroll
    for (int o = 16; o > 0; o >>= 1) mx = fmaxf(mx, __shfl_xor_sync(0xFFFFFFFFu, mx, o));
    float sum = 0.f;
#pragma unroll
    for (int k = 0; k < 8; ++k) { lv[k] = expf(lv[k] - mx); sum += lv[k]; }
#pragma unroll
    for (int o = 16; o > 0; o >>= 1) sum += __shfl_xor_sync(0xFFFFFFFFu, sum, o);
    float inv = 1.f / sum;
#pragma unroll
    for (int k = 0; k < 8; ++k) g_at[n*2048 + (l + k*32)*8 + w] = lv[k] * inv;
}

// ---------------- 4c) G partial sums: grid (NQ, 2) --------------------------
__global__ void __launch_bounds__(256)
k_g()
{
    __shared__ float at[128*8];
    int n = blockIdx.x, half = blockIdx.y, t = threadIdx.x;
    for (int i = t; i < 1024; i += 256) at[i] = g_at[n*2048 + half*1024 + i];
    __syncthreads();
    float acc[8] = {0,0,0,0,0,0,0,0};
    int base = n*SSN + half*128;
#pragma unroll 4
    for (int s = 0; s < 128; ++s) {
        float fv = g_f[((size_t)(base + s))*DD + t];
#pragma unroll
        for (int h = 0; h < 8; ++h) acc[h] += at[s*8 + h] * fv;
    }
#pragma unroll
    for (int h = 0; h < 8; ++h) g_gp[half][n*2048 + h*DD + t] = acc[h];
}

// ---------------- 5) slot path: o, delta, LN, slot-MLP, slotc ---------------
__global__ void __launch_bounds__(256)
k_slotpath(const float* __restrict__ slots, const float* __restrict__ ipw,
           const float* __restrict__ ipb, const float* __restrict__ opw,
           const float* __restrict__ opb, const float* __restrict__ lng,
           const float* __restrict__ lnb, const float* __restrict__ sw1,
           const float* __restrict__ sb1, const float* __restrict__ sw2,
           const float* __restrict__ sb2, const float* __restrict__ gw1,
           const float* __restrict__ gb1, float* __restrict__ out)
{
    __shared__ float G[2048], ov[256], so[256], hid[128], ps[128], red[8];
    int n = blockIdx.x, t = threadIdx.x;
    for (int i = t; i < 2048; i += 256)
        G[i] = g_gp[0][n*2048 + i] + g_gp[1][n*2048 + i];
    __syncthreads();
    {
        int h = t >> 5;
        const float* wr = ipw + (size_t)(512 + t) * DD;
        float a = ipb[512 + t];
#pragma unroll 8
        for (int e = 0; e < DD; e += 4) {
            float4 w4 = *(const float4*)(wr + e);
            a += w4.x*G[h*256+e] + w4.y*G[h*256+e+1] + w4.z*G[h*256+e+2] + w4.w*G[h*256+e+3];
        }
        ov[t] = a;
    }
    __syncthreads();
    float x;
    {
        const float* wr = opw + (size_t)t * DD;
        float a = opb[t];
#pragma unroll 8
        for (int e = 0; e < DD; e += 4) {
            float4 w4 = *(const float4*)(wr + e);
            a += w4.x*ov[e] + w4.y*ov[e+1] + w4.z*ov[e+2] + w4.w*ov[e+3];
        }
        x = slots[n*DD + t] + a;
    }
    float v = x;
#pragma unroll
    for (int o = 16; o > 0; o >>= 1) v += __shfl_xor_sync(0xFFFFFFFFu, v, o);
    if ((t & 31) == 0) red[t >> 5] = v;
    __syncthreads();
    float mu = 0.f;
#pragma unroll
    for (int i = 0; i < 8; ++i) mu += red[i];
    mu *= (1.f/256.f);
    __syncthreads();
    float d = x - mu; v = d * d;
#pragma unroll
    for (int o = 16; o > 0; o >>= 1) v += __shfl_xor_sync(0xFFFFFFFFu, v, o);
    if ((t & 31) == 0) red[t >> 5] = v;
    __syncthreads();
    float var = 0.f;
#pragma unroll
    for (int i = 0; i < 8; ++i) var += red[i];
    var *= (1.f/256.f);
    float sov = d * rsqrtf(var + 1e-5f) * lng[t] + lnb[t];
    so[t] = sov;
    out[n*DD + t] = sov;
    __syncthreads();
    if (t < 128) {
        const float* wr = sw1 + (size_t)t * DD;
        float a = sb1[t];
#pragma unroll 8
        for (int e = 0; e < DD; e += 4) {
            float4 w4 = *(const float4*)(wr + e);
            a += w4.x*so[e] + w4.y*so[e+1] + w4.z*so[e+2] + w4.w*so[e+3];
        }
        hid[t] = fmaxf(a, 0.f);
    }
    __syncthreads();
    if (t < 128) {
        const float* wr = sw2 + (size_t)t * 128;
        float a = sb2[t];
#pragma unroll 8
        for (int e = 0; e < 128; e += 4) {
            float4 w4 = *(const float4*)(wr + e);
            a += w4.x*hid[e] + w4.y*hid[e+1] + w4.z*hid[e+2] + w4.w*hid[e+3];
        }
        ps[t] = a;
    }
    __syncthreads();
    {
        const float* wr = gw1 + (size_t)t * DD;
        float a = gb1[t];
#pragma unroll 8
        for (int i = 0; i < 128; i += 4) {
            float4 w4 = *(const float4*)(wr + i);
            a += w4.x*ps[i] + w4.y*ps[i+1] + w4.z*ps[i+2] + w4.w*ps[i+3];
        }
        g_slotc[n*DD + t] = a;
    }
}

// ---------------- 6) fused featMLP(L1,L2) + seg inner GEMM, tf32 MMA --------
// Block = 128 rows; 8 warps in 4(m) x 2(n) layout; warp tile 32x64.
#define HP 132
#define SP 36
#define FU_SMEM ((128*HP + 2*128*SP)*4)

__global__ void __launch_bounds__(256, 1)
k_fused(const float* __restrict__ fw1, const float* __restrict__ fb1,
        const float* __restrict__ fw2, const float* __restrict__ fb2,
        const float* __restrict__ gw1)
{
    extern __shared__ float sm[];
    float* H  = sm;               // 128 x HP (layer1 out, then pf)
    float* As = sm + 128*HP;      // 128 x SP
    float* Bs = As + 128*SP;      // 128 x SP
    const int t = threadIdx.x, lane = t & 31, w = t >> 5;
    const int r0 = blockIdx.x * 128, n = blockIdx.x >> 1;
    const int wm = (w & 3) * 32, wn = (w >> 2) * 64;
    const int g = lane >> 2, tg = lane & 3;

    float c[2][8][4];
#pragma unroll
    for (int mi = 0; mi < 2; ++mi)
#pragma unroll
        for (int nj = 0; nj < 8; ++nj)
#pragma unroll
            for (int q = 0; q < 4; ++q) c[mi][nj][q] = 0.f;

    // ---- layer 1: H = relu(keys @ fw1^T + fb1), K=256 ----
    for (int kc = 0; kc < 256; kc += 32) {
#pragma unroll
        for (int m = 0; m < 16; ++m) {
            int idx = m*256 + t, row = idx >> 5, kk = idx & 31;
            As[row*SP+kk] = __uint_as_float(rna(g_keys[(size_t)(r0+row)*DD + kc + kk]));
            Bs[row*SP+kk] = __uint_as_float(rna(fw1[(size_t)row*DD + kc + kk]));
        }
        __syncthreads();
#pragma unroll
        for (int k0 = 0; k0 < 32; k0 += 8) {
            unsigned a[2][4], b[8][2];
#pragma unroll
            for (int mi = 0; mi < 2; ++mi) {
                int rr = wm + mi*16 + g;
                a[mi][0] = __float_as_uint(As[rr*SP + k0+tg]);
                a[mi][1] = __float_as_uint(As[(rr+8)*SP + k0+tg]);
                a[mi][2] = __float_as_uint(As[rr*SP + k0+tg+4]);
                a[mi][3] = __float_as_uint(As[(rr+8)*SP + k0+tg+4]);
            }
#pragma unroll
            for (int nj = 0; nj < 8; ++nj) {
                int nr = wn + nj*8 + g;
                b[nj][0] = __float_as_uint(Bs[nr*SP + k0+tg]);
                b[nj][1] = __float_as_uint(Bs[nr*SP + k0+tg+4]);
            }
#pragma unroll
            for (int mi = 0; mi < 2; ++mi)
#pragma unroll
                for (int nj = 0; nj < 8; ++nj) mma_tf32(c[mi][nj], a[mi], b[nj]);
        }
        __syncthreads();
    }
#pragma unroll
    for (int mi = 0; mi < 2; ++mi)
#pragma unroll
        for (int nj = 0; nj < 8; ++nj) {
            int rA = wm + mi*16 + g, cc = wn + nj*8 + 2*tg;
            H[rA*HP+cc]       = __uint_as_float(rna(fmaxf(c[mi][nj][0] + __ldg(fb1+cc),   0.f)));
            H[rA*HP+cc+1]     = __uint_as_float(rna(fmaxf(c[mi][nj][1] + __ldg(fb1+cc+1), 0.f)));
            H[(rA+8)*HP+cc]   = __uint_as_float(rna(fmaxf(c[mi][nj][2] + __ldg(fb1+cc),   0.f)));
            H[(rA+8)*HP+cc+1] = __uint_as_float(rna(fmaxf(c[mi][nj][3] + __ldg(fb1+cc+1), 0.f)));
#pragma unroll
            for (int q = 0; q < 4; ++q) c[mi][nj][q] = 0.f;
        }
    __syncthreads();

    // ---- layer 2: pf = H @ fw2^T + fb2, K=128, A = H (in smem) ----
    for (int kc = 0; kc < 128; kc += 32) {
#pragma unroll
        for (int m = 0; m < 16; ++m) {
            int idx = m*256 + t, row = idx >> 5, kk = idx & 31;
            Bs[row*SP+kk] = __uint_as_float(rna(fw2[(size_t)row*128 + kc + kk]));
        }
        __syncthreads();
#pragma unroll
        for (int k0 = 0; k0 < 32; k0 += 8) {
            unsigned a[2][4], b[8][2];
#pragma unroll
            for (int mi = 0; mi < 2; ++mi) {
                int rr = wm + mi*16 + g;
                a[mi][0] = __float_as_uint(H[rr*HP + kc+k0+tg]);
                a[mi][1] = __float_as_uint(H[(rr+8)*HP + kc+k0+tg]);
                a[mi][2] = __float_as_uint(H[rr*HP + kc+k0+tg+4]);
                a[mi][3] = __float_as_uint(H[(rr+8)*HP + kc+k0+tg+4]);
            }
#pragma unroll
            for (int nj = 0; nj < 8; ++nj) {
                int nr = wn + nj*8 + g;
                b[nj][0] = __float_as_uint(Bs[nr*SP + k0+tg]);
                b[nj][1] = __float_as_uint(Bs[nr*SP + k0+tg+4]);
            }
#pragma unroll
            for (int mi = 0; mi < 2; ++mi)
#pragma unroll
                for (int nj = 0; nj < 8; ++nj) mma_tf32(c[mi][nj], a[mi], b[nj]);
        }
        __syncthreads();
    }
    // overwrite H with tf32-rounded pf (all reads done: loop ends with sync)
    {
        float pfv[2][8][4];
#pragma unroll
        for (int mi = 0; mi < 2; ++mi)
#pragma unroll
            for (int nj = 0; nj < 8; ++nj) {
                int cc = wn + nj*8 + 2*tg;
                pfv[mi][nj][0] = c[mi][nj][0] + __ldg(fb2+cc);
                pfv[mi][nj][1] = c[mi][nj][1] + __ldg(fb2+cc+1);
                pfv[mi][nj][2] = c[mi][nj][2] + __ldg(fb2+cc);
                pfv[mi][nj][3] = c[mi][nj][3] + __ldg(fb2+cc+1);
            }
        __syncthreads();
#pragma unroll
        for (int mi = 0; mi < 2; ++mi)
#pragma unroll
            for (int nj = 0; nj < 8; ++nj) {
                int rA = wm + mi*16 + g, cc = wn + nj*8 + 2*tg;
                H[rA*HP+cc]       = __uint_as_float(rna(pfv[mi][nj][0]));
                H[rA*HP+cc+1]     = __uint_as_float(rna(pfv[mi][nj][1]));
                H[(rA+8)*HP+cc]   = __uint_as_float(rna(pfv[mi][nj][2]));
                H[(rA+8)*HP+cc+1] = __uint_as_float(rna(pfv[mi][nj][3]));
            }
    }
    __syncthreads();

    // ---- layer 3 (seg inner): s1 = relu(pf @ gw1[:,128:]^T + slotc), 2 halves
    for (int jh = 0; jh < 2; ++jh) {
#pragma unroll
        for (int mi = 0; mi < 2; ++mi)
#pragma unroll
            for (int nj = 0; nj < 8; ++nj)
#pragma unroll
                for (int q = 0; q < 4; ++q) c[mi][nj][q] = 0.f;
        for (int kc = 0; kc < 128; kc += 32) {
#pragma unroll
            for (int m = 0; m < 16; ++m) {
                int idx = m*256 + t, row = idx >> 5, kk = idx & 31;
                Bs[row*SP+kk] = __uint_as_float(
                    rna(gw1[(size_t)(jh*128+row)*DD + 128 + kc + kk]));
            }
            __syncthreads();
#pragma unroll
            for (int k0 = 0; k0 < 32; k0 += 8) {
                unsigned a[2][4], b[8][2];
#pragma unroll
                for (int mi = 0; mi < 2; ++mi) {
                    int rr = wm + mi*16 + g;
                    a[mi][0] = __float_as_uint(H[rr*HP + kc+k0+tg]);
                    a[mi][1] = __float_as_uint(H[(rr+8)*HP + kc+k0+tg]);
                    a[mi][2] = __float_as_uint(H[rr*HP + kc+k0+tg+4]);
                    a[mi][3] = __float_as_uint(H[(rr+8)*HP + kc+k0+tg+4]);
                }
#pragma unroll
                for (int nj = 0; nj < 8; ++nj) {
                    int nr = wn + nj*8 + g;
                    b[nj][0] = __float_as_uint(Bs[nr*SP + k0+tg]);
                    b[nj][1] = __float_as_uint(Bs[nr*SP + k0+tg+4]);
                }
#pragma unroll
                for (int mi = 0; mi < 2; ++mi)
#pragma unroll
                    for (int nj = 0; nj < 8; ++nj) mma_tf32(c[mi][nj], a[mi], b[nj]);
            }
            __syncthreads();
        }
#pragma unroll
        for (int mi = 0; mi < 2; ++mi)
#pragma unroll
            for (int nj = 0; nj < 8; ++nj) {
                int rA = r0 + wm + mi*16 + g;
                int cj = jh*128 + wn + nj*8 + 2*tg;
                float s0 = __ldg(g_slotc + n*DD + cj);
                float s1v = __ldg(g_slotc + n*DD + cj + 1);
                g_s1[(size_t)rA*DD + cj]       = fmaxf(c[mi][nj][0] + s0,  0.f);
                g_s1[(size_t)rA*DD + cj + 1]   = fmaxf(c[mi][nj][1] + s1v, 0.f);
                g_s1[(size_t)(rA+8)*DD + cj]   = fmaxf(c[mi][nj][2] + s0,  0.f);
                g_s1[(size_t)(rA+8)*DD + cj+1] = fmaxf(c[mi][nj][3] + s1v, 0.f);
            }
    }
}

// ---------------- 7) seg head: 3-way GEMV + softmax + write + scatter -------
__global__ void __launch_bounds__(256)
k_seg2(const float* __restrict__ gw2, const float* __restrict__ gb2,
       float* __restrict__ out)
{
    int w = threadIdx.x >> 5, l = threadIdx.x & 31;
    int r = blockIdx.x * 8 + w;
    int n = r >> 8, s = r & 255;
    const float* inr = g_s1 + (size_t)r * DD;
    float a0 = 0.f, a1 = 0.f, a2 = 0.f;
#pragma unroll
    for (int k = l; k < DD; k += 32) {
        float x = inr[k];
        a0 += x * __ldg(gw2 + k);
        a1 += x * __ldg(gw2 + 256 + k);
        a2 += x * __ldg(gw2 + 512 + k);
    }
#pragma unroll
    for (int o = 16; o > 0; o >>= 1) {
        a0 += __shfl_xor_sync(0xFFFFFFFFu, a0, o);
        a1 += __shfl_xor_sync(0xFFFFFFFFu, a1, o);
        a2 += __shfl_xor_sync(0xFFFFFFFFu, a2, o);
    }
    if (l == 0) {
        a0 += gb2[0]; a1 += gb2[1]; a2 += gb2[2];
        float m = fmaxf(a0, fmaxf(a1, a2));
        float e0 = expf(a0 - m), e1 = expf(a1 - m), e2 = expf(a2 - m);
        float inv = 1.f / (e0 + e1 + e2);
        e0 *= inv; e1 *= inv; e2 *= inv;
        size_t pb = (size_t)65536 + 12582912 + ((size_t)s*256 + n)*3;
        out[pb] = e0; out[pb+1] = e1; out[pb+2] = e2;
        int i = g_feat_idx[r];
        size_t sb = (size_t)65536 + (size_t)n*49152 + i;
        out[sb] = e0; out[sb + 16384] = e1; out[sb + 32768] = e2;
    }
}

// ---------------------------------------------------------------------------
extern "C" void kernel_launch(void* const* d_in, const int* in_sizes, int n_in,
                              void* d_out, int out_size)
{
    const float* features = (const float*)d_in[0];
    const float* pos      = (const float*)d_in[1];
    const int*   bidx     = (const int*)d_in[2];
    const float* curio    = (const float*)d_in[3];
    const float* slots    = (const float*)d_in[5];
    const int*   cov_sel  = (const int*)d_in[6];
    const float* ipw = (const float*)d_in[7];
    const float* ipb = (const float*)d_in[8];
    const float* opw = (const float*)d_in[9];
    const float* opb = (const float*)d_in[10];
    const float* lng = (const float*)d_in[11];
    const float* lnb = (const float*)d_in[12];
    const float* sw1 = (const float*)d_in[13];
    const float* sb1 = (const float*)d_in[14];
    const float* sw2 = (const float*)d_in[15];
    const float* sb2 = (const float*)d_in[16];
    const float* fw1 = (const float*)d_in[17];
    const float* fb1 = (const float*)d_in[18];
    const float* fw2 = (const float*)d_in[19];
    const float* fb2 = (const float*)d_in[20];
    const float* gw1 = (const float*)d_in[21];
    const float* gb1 = (const float*)d_in[22];
    const float* gw2 = (const float*)d_in[23];
    const float* gb2 = (const float*)d_in[24];
    float* out = (float*)d_out;

    cudaFuncSetAttribute(k_sort, cudaFuncAttributeMaxDynamicSharedMemorySize,
                         (int)sizeof(SortSmem));
    cudaFuncSetAttribute(k_fused, cudaFuncAttributeMaxDynamicSharedMemorySize, FU_SMEM);

    cudaMemsetAsync(d_out, 0, (size_t)out_size * sizeof(float));
    // 3 no-op launches: the profiler captures the 4th kernel -> k_sort next round
    k_nop<<<1, 1>>>();
    k_nop<<<1, 1>>>();
    k_nop<<<1, 1>>>();
    k_sort<<<NQ, 512, sizeof(SortSmem)>>>(curio, cov_sel);
    k_gather<<<RTOT/8, 256>>>(features, pos, bidx);
    k_qprep<<<NQ, 256>>>(slots, ipw, ipb);
    dim3 glog(NQ, 4);
    k_logits<<<glog, 256, LG_SMEM>>>();
    k_soft<<<NQ, 256>>>();
    dim3 gg(NQ, 2);
    k_g<<<gg, 256>>>();
    k_slotpath<<<NQ, 256>>>(slots, ipw, ipb, opw, opb, lng, lnb,
                            sw1, sb1, sw2, sb2, gw1, gb1, out);
    k_fused<<<RTOT/128, 256, FU_SMEM>>>(fw1, fb1, fw2, fb2, gw1);
    k_seg2<<<RTOT/8, 256>>>(gw2, gb2, out);
}

// round 11
// speedup vs baseline: 1.6367x; 1.0888x over previous
#include <cuda_runtime.h>
#include <cuda_bf16.h>
#include <cstdint>
#include <math.h>
#include <cub/block/block_radix_sort.cuh>

#define NQ 256
#define SSN 256
#define DD 256
#define HWT 16384
#define RTOT (NQ*SSN)

// ---------------- scratch (device globals; no allocation allowed) -----------
__device__ __align__(16) int   g_feat_idx[RTOT];
__device__ __align__(16) float g_keys[RTOT*DD];
__device__ __align__(16) float g_qw[NQ*8*DD];
__device__ __align__(16) float g_gp[2][NQ*8*DD];
__device__ __align__(16) float g_slotc[NQ*DD];
__device__ __align__(16) float g_lg[NQ*8*SSN];
__device__ __align__(16) float g_at[NQ*SSN*8];

// ---------------- tf32 mma helpers ------------------------------------------
__device__ __forceinline__ unsigned rna(float x) {
    unsigned o; asm("cvt.rna.tf32.f32 %0, %1;" : "=r"(o) : "f"(x)); return o;
}
__device__ __forceinline__ void mma_tf32(float* c, const unsigned* a, const unsigned* b) {
    asm volatile("mma.sync.aligned.m16n8k8.row.col.f32.tf32.tf32.f32 "
        "{%0,%1,%2,%3}, {%4,%5,%6,%7}, {%8,%9}, {%0,%1,%2,%3};"
        : "+f"(c[0]), "+f"(c[1]), "+f"(c[2]), "+f"(c[3])
        : "r"(a[0]), "r"(a[1]), "r"(a[2]), "r"(a[3]), "r"(b[0]), "r"(b[1]));
}

// ---------------- profiling alignment dummies --------------------------------
__global__ void k_nop() {}

// ---------------- 1) per-row stable descending argsort + rank select --------
// Stable radix SortDescending on mono(float) keys with u16 idx payload:
// ties keep input (idx-ascending) order == jnp.argsort(-x) exactly.
// RADIX_BITS=6 -> 6 passes over 32 bits instead of 8 (default 4 bits/pass).
using Sorter = cub::BlockRadixSort<unsigned, 512, 32, unsigned short, 6>;
struct SortSmem { union { Sorter::TempStorage ts; unsigned short sidx[HWT]; }; };

__global__ void __launch_bounds__(512, 1)
k_sort(const float* __restrict__ curio, const int* __restrict__ cov_sel)
{
    extern __shared__ char raw[];
    SortSmem& sm = *reinterpret_cast<SortSmem*>(raw);
    const int n = blockIdx.x;
    const float* row = curio + (size_t)n * HWT;
    unsigned k[32]; unsigned short v[32];
    const int base = threadIdx.x * 32;
#pragma unroll
    for (int j = 0; j < 32; ++j) {
        unsigned u = __float_as_uint(row[base + j]);
        k[j] = u ^ (((unsigned)((int)u >> 31)) | 0x80000000u);
        v[j] = (unsigned short)(base + j);
    }
    Sorter(sm.ts).SortDescending(k, v, 0, 32);
    __syncthreads();
#pragma unroll
    for (int j = 0; j < 32; ++j) sm.sidx[base + j] = v[j];
    __syncthreads();
    if (threadIdx.x < SSN) {
        int s = threadIdx.x;
        int rank = (s < 192) ? s : 192 + cov_sel[s - 192];
        g_feat_idx[n * SSN + s] = (int)sm.sidx[rank];
    }
}

// ---------------- 2) gather keys = f + p (warp per row) ---------------------
__global__ void __launch_bounds__(256)
k_gather(const float* __restrict__ feat, const float* __restrict__ pos,
         const int* __restrict__ bidx)
{
    int w = threadIdx.x >> 5, l = threadIdx.x & 31;
    int r = blockIdx.x * 8 + w;
    int n = r >> 8;
    int i = g_feat_idx[r];
    int b = bidx[n];
    size_t src = ((size_t)i * 8 + b) * DD;
    size_t dst = (size_t)r * DD;
#pragma unroll
    for (int c = 0; c < 2; ++c) {
        int e = (l + c * 32) * 4;
        float4 fv = *(const float4*)(feat + src + e);
        float4 pv = *(const float4*)(pos + src + e);
        *(float4*)(g_keys + dst + e) =
            make_float4(fv.x + pv.x, fv.y + pv.y, fv.z + pv.z, fv.w + pv.w);
    }
}

// ---------------- 3) q, then qw = q@wk folded -------------------------------
__global__ void __launch_bounds__(256)
k_qprep(const float* __restrict__ slots, const float* __restrict__ ipw,
        const float* __restrict__ ipb)
{
    __shared__ float sl[DD], qs[DD];
    int n = blockIdx.x, t = threadIdx.x;
    sl[t] = slots[n * DD + t];
    __syncthreads();
    {
        const float* wr = ipw + (size_t)t * DD;
        float a = ipb[t];
#pragma unroll 8
        for (int e = 0; e < DD; e += 4) {
            float4 w4 = *(const float4*)(wr + e);
            a += w4.x*sl[e] + w4.y*sl[e+1] + w4.z*sl[e+2] + w4.w*sl[e+3];
        }
        qs[t] = a * 0.17677669529663687f;
    }
    __syncthreads();
    for (int h = 0; h < 8; ++h) {
        float a = 0.f;
#pragma unroll
        for (int d = 0; d < 32; ++d) {
            int hd = h * 32 + d;
            a += qs[hd] * __ldg(ipw + (size_t)(DD + hd) * DD + t);
        }
        g_qw[n * 2048 + h * DD + t] = a;
    }
}

// ---------------- 4a) logits: grid (NQ, 4) ----------------------------------
#define LG_SMEM ((8*260 + 32*260)*4)
__global__ void __launch_bounds__(256)
k_logits()
{
    extern __shared__ float sm[];
    float* qw_s = sm;
    float* ks   = sm + 8*260;
    const int n = blockIdx.x, q = blockIdx.y, t = threadIdx.x;
    for (int i = t; i < 2048; i += 256)
        qw_s[(i >> 8)*260 + (i & 255)] = g_qw[n*2048 + i];
    const int sl = t >> 3, h = t & 7;
#pragma unroll
    for (int c = 0; c < 2; ++c) {
        int s0 = q*64 + c*32;
        __syncthreads();
        for (int i = t; i < 32*64; i += 256) {
            int row = i >> 6, e4 = (i & 63)*4;
            *(float4*)(ks + row*260 + e4) =
                *(const float4*)(g_keys + ((size_t)(n*SSN + s0 + row))*DD + e4);
        }
        __syncthreads();
        float a = 0.f;
#pragma unroll 8
        for (int e = 0; e < DD; e += 4) {
            float4 kv = *(float4*)(ks + sl*260 + e);
            float4 qv = *(float4*)(qw_s + h*260 + e);
            a += kv.x*qv.x + kv.y*qv.y + kv.z*qv.z + kv.w*qv.w;
        }
        g_lg[n*2048 + h*SSN + s0 + sl] = a;
    }
}

// ---------------- 4b) softmax over s per (n,h) ------------------------------
__global__ void __launch_bounds__(256)
k_soft()
{
    int n = blockIdx.x, t = threadIdx.x, w = t >> 5, l = t & 31;
    float lv[8]; float mx = -1e30f;
#pragma unroll
    for (int k = 0; k < 8; ++k) {
        lv[k] = g_lg[n*2048 + w*SSN + l + k*32];
        mx = fmaxf(mx, lv[k]);
    }
#pragma unroll
    for (int o = 16; o > 0; o >>= 1) mx = fmaxf(mx, __shfl_xor_sync(0xFFFFFFFFu, mx, o));
    float sum = 0.f;
#pragma unroll
    for (int k = 0; k < 8; ++k) { lv[k] = expf(lv[k] - mx); sum += lv[k]; }
#pragma unroll
    for (int o = 16; o > 0; o >>= 1) sum += __shfl_xor_sync(0xFFFFFFFFu, sum, o);
    float inv = 1.f / sum;
#pragma unroll
    for (int k = 0; k < 8; ++k) g_at[n*2048 + (l + k*32)*8 + w] = lv[k] * inv;
}

// ---------------- 4c) G partial sums: grid (NQ, 2), gathers features --------
__global__ void __launch_bounds__(256)
k_g(const float* __restrict__ feat, const int* __restrict__ bidx)
{
    __shared__ float at[128*8];
    __shared__ int sidx[128];
    int n = blockIdx.x, half = blockIdx.y, t = threadIdx.x;
    for (int i = t; i < 1024; i += 256) at[i] = g_at[n*2048 + half*1024 + i];
    if (t < 128) sidx[t] = g_feat_idx[n*SSN + half*128 + t];
    __syncthreads();
    int b = bidx[n];
    float acc[8] = {0,0,0,0,0,0,0,0};
#pragma unroll 4
    for (int s = 0; s < 128; ++s) {
        float fv = feat[((size_t)sidx[s]*8 + b)*DD + t];
#pragma unroll
        for (int h = 0; h < 8; ++h) acc[h] += at[s*8 + h] * fv;
    }
#pragma unroll
    for (int h = 0; h < 8; ++h) g_gp[half][n*2048 + h*DD + t] = acc[h];
}

// ---------------- 5) slot path: o, delta, LN, slot-MLP, slotc ---------------
__global__ void __launch_bounds__(256)
k_slotpath(const float* __restrict__ slots, const float* __restrict__ ipw,
           const float* __restrict__ ipb, const float* __restrict__ opw,
           const float* __restrict__ opb, const float* __restrict__ lng,
           const float* __restrict__ lnb, const float* __restrict__ sw1,
           const float* __restrict__ sb1, const float* __restrict__ sw2,
           const float* __restrict__ sb2, const float* __restrict__ gw1,
           const float* __restrict__ gb1, float* __restrict__ out)
{
    __shared__ float G[2048], ov[256], so[256], hid[128], ps[128], red[8];
    int n = blockIdx.x, t = threadIdx.x;
    for (int i = t; i < 2048; i += 256)
        G[i] = g_gp[0][n*2048 + i] + g_gp[1][n*2048 + i];
    __syncthreads();
    {
        int h = t >> 5;
        const float* wr = ipw + (size_t)(512 + t) * DD;
        float a = ipb[512 + t];
#pragma unroll 8
        for (int e = 0; e < DD; e += 4) {
            float4 w4 = *(const float4*)(wr + e);
            a += w4.x*G[h*256+e] + w4.y*G[h*256+e+1] + w4.z*G[h*256+e+2] + w4.w*G[h*256+e+3];
        }
        ov[t] = a;
    }
    __syncthreads();
    float x;
    {
        const float* wr = opw + (size_t)t * DD;
        float a = opb[t];
#pragma unroll 8
        for (int e = 0; e < DD; e += 4) {
            float4 w4 = *(const float4*)(wr + e);
            a += w4.x*ov[e] + w4.y*ov[e+1] + w4.z*ov[e+2] + w4.w*ov[e+3];
        }
        x = slots[n*DD + t] + a;
    }
    float v = x;
#pragma unroll
    for (int o = 16; o > 0; o >>= 1) v += __shfl_xor_sync(0xFFFFFFFFu, v, o);
    if ((t & 31) == 0) red[t >> 5] = v;
    __syncthreads();
    float mu = 0.f;
#pragma unroll
    for (int i = 0; i < 8; ++i) mu += red[i];
    mu *= (1.f/256.f);
    __syncthreads();
    float d = x - mu; v = d * d;
#pragma unroll
    for (int o = 16; o > 0; o >>= 1) v += __shfl_xor_sync(0xFFFFFFFFu, v, o);
    if ((t & 31) == 0) red[t >> 5] = v;
    __syncthreads();
    float var = 0.f;
#pragma unroll
    for (int i = 0; i < 8; ++i) var += red[i];
    var *= (1.f/256.f);
    float sov = d * rsqrtf(var + 1e-5f) * lng[t] + lnb[t];
    so[t] = sov;
    out[n*DD + t] = sov;
    __syncthreads();
    if (t < 128) {
        const float* wr = sw1 + (size_t)t * DD;
        float a = sb1[t];
#pragma unroll 8
        for (int e = 0; e < DD; e += 4) {
            float4 w4 = *(const float4*)(wr + e);
            a += w4.x*so[e] + w4.y*so[e+1] + w4.z*so[e+2] + w4.w*so[e+3];
        }
        hid[t] = fmaxf(a, 0.f);
    }
    __syncthreads();
    if (t < 128) {
        const float* wr = sw2 + (size_t)t * 128;
        float a = sb2[t];
#pragma unroll 8
        for (int e = 0; e < 128; e += 4) {
            float4 w4 = *(const float4*)(wr + e);
            a += w4.x*hid[e] + w4.y*hid[e+1] + w4.z*hid[e+2] + w4.w*hid[e+3];
        }
        ps[t] = a;
    }
    __syncthreads();
    {
        const float* wr = gw1 + (size_t)t * DD;
        float a = gb1[t];
#pragma unroll 8
        for (int i = 0; i < 128; i += 4) {
            float4 w4 = *(const float4*)(wr + i);
            a += w4.x*ps[i] + w4.y*ps[i+1] + w4.z*ps[i+2] + w4.w*ps[i+3];
        }
        g_slotc[n*DD + t] = a;
    }
}

// ---------------- 6) fused featMLP(L1,L2) + seg GEMM + seg head -------------
// Block = 128 rows; 8 warps in 4(m) x 2(n) layout; warp tile 32x64.
// Epilogue applies the 3-class GEMV (gw2), softmax, and scatters to out.
#define HP 132
#define SP 36
#define FU_FLOATS (128*HP + 2*128*SP + 256 + 768 + 768)
#define FU_SMEM (FU_FLOATS*4)

__global__ void __launch_bounds__(256, 1)
k_fused(const float* __restrict__ fw1, const float* __restrict__ fb1,
        const float* __restrict__ fw2, const float* __restrict__ fb2,
        const float* __restrict__ gw1, const float* __restrict__ gw2,
        const float* __restrict__ gb2, float* __restrict__ out)
{
    extern __shared__ float sm[];
    float* H     = sm;                      // 128 x HP (layer1 out, then pf)
    float* As    = sm + 128*HP;             // 128 x SP
    float* Bs    = As + 128*SP;             // 128 x SP
    float* sslot = Bs + 128*SP;             // 256 (slotc row for this n)
    float* sgw2  = sslot + 256;             // 3 x 256
    float* part  = sgw2 + 768;              // 128 x 2 x 3
    const int t = threadIdx.x, lane = t & 31, w = t >> 5;
    const int r0 = blockIdx.x * 128, n = blockIdx.x >> 1;
    const int wm = (w & 3) * 32, wn = (w >> 2) * 64;
    const int g = lane >> 2, tg = lane & 3;

    sslot[t] = g_slotc[n*DD + t];
    for (int i = t; i < 768; i += 256) sgw2[i] = __ldg(gw2 + i);

    float c[2][8][4];
#pragma unroll
    for (int mi = 0; mi < 2; ++mi)
#pragma unroll
        for (int nj = 0; nj < 8; ++nj)
#pragma unroll
            for (int q = 0; q < 4; ++q) c[mi][nj][q] = 0.f;

    // ---- layer 1: H = relu(keys @ fw1^T + fb1), K=256 ----
    for (int kc = 0; kc < 256; kc += 32) {
#pragma unroll
        for (int m = 0; m < 16; ++m) {
            int idx = m*256 + t, row = idx >> 5, kk = idx & 31;
            As[row*SP+kk] = __uint_as_float(rna(g_keys[(size_t)(r0+row)*DD + kc + kk]));
            Bs[row*SP+kk] = __uint_as_float(rna(fw1[(size_t)row*DD + kc + kk]));
        }
        __syncthreads();
#pragma unroll
        for (int k0 = 0; k0 < 32; k0 += 8) {
            unsigned a[2][4], b[8][2];
#pragma unroll
            for (int mi = 0; mi < 2; ++mi) {
                int rr = wm + mi*16 + g;
                a[mi][0] = __float_as_uint(As[rr*SP + k0+tg]);
                a[mi][1] = __float_as_uint(As[(rr+8)*SP + k0+tg]);
                a[mi][2] = __float_as_uint(As[rr*SP + k0+tg+4]);
                a[mi][3] = __float_as_uint(As[(rr+8)*SP + k0+tg+4]);
            }
#pragma unroll
            for (int nj = 0; nj < 8; ++nj) {
                int nr = wn + nj*8 + g;
                b[nj][0] = __float_as_uint(Bs[nr*SP + k0+tg]);
                b[nj][1] = __float_as_uint(Bs[nr*SP + k0+tg+4]);
            }
#pragma unroll
            for (int mi = 0; mi < 2; ++mi)
#pragma unroll
                for (int nj = 0; nj < 8; ++nj) mma_tf32(c[mi][nj], a[mi], b[nj]);
        }
        __syncthreads();
    }
#pragma unroll
    for (int mi = 0; mi < 2; ++mi)
#pragma unroll
        for (int nj = 0; nj < 8; ++nj) {
            int rA = wm + mi*16 + g, cc = wn + nj*8 + 2*tg;
            H[rA*HP+cc]       = __uint_as_float(rna(fmaxf(c[mi][nj][0] + __ldg(fb1+cc),   0.f)));
            H[rA*HP+cc+1]     = __uint_as_float(rna(fmaxf(c[mi][nj][1] + __ldg(fb1+cc+1), 0.f)));
            H[(rA+8)*HP+cc]   = __uint_as_float(rna(fmaxf(c[mi][nj][2] + __ldg(fb1+cc),   0.f)));
            H[(rA+8)*HP+cc+1] = __uint_as_float(rna(fmaxf(c[mi][nj][3] + __ldg(fb1+cc+1), 0.f)));
#pragma unroll
            for (int q = 0; q < 4; ++q) c[mi][nj][q] = 0.f;
        }
    __syncthreads();

    // ---- layer 2: pf = H @ fw2^T + fb2, K=128, A = H (in smem) ----
    for (int kc = 0; kc < 128; kc += 32) {
#pragma unroll
        for (int m = 0; m < 16; ++m) {
            int idx = m*256 + t, row = idx >> 5, kk = idx & 31;
            Bs[row*SP+kk] = __uint_as_float(rna(fw2[(size_t)row*128 + kc + kk]));
        }
        __syncthreads();
#pragma unroll
        for (int k0 = 0; k0 < 32; k0 += 8) {
            unsigned a[2][4], b[8][2];
#pragma unroll
            for (int mi = 0; mi < 2; ++mi) {
                int rr = wm + mi*16 + g;
                a[mi][0] = __float_as_uint(H[rr*HP + kc+k0+tg]);
                a[mi][1] = __float_as_uint(H[(rr+8)*HP + kc+k0+tg]);
                a[mi][2] = __float_as_uint(H[rr*HP + kc+k0+tg+4]);
                a[mi][3] = __float_as_uint(H[(rr+8)*HP + kc+k0+tg+4]);
            }
#pragma unroll
            for (int nj = 0; nj < 8; ++nj) {
                int nr = wn + nj*8 + g;
                b[nj][0] = __float_as_uint(Bs[nr*SP + k0+tg]);
                b[nj][1] = __float_as_uint(Bs[nr*SP + k0+tg+4]);
            }
#pragma unroll
            for (int mi = 0; mi < 2; ++mi)
#pragma unroll
                for (int nj = 0; nj < 8; ++nj) mma_tf32(c[mi][nj], a[mi], b[nj]);
        }
        __syncthreads();
    }
    // overwrite H with tf32-rounded pf (all reads done: loop ends with sync)
    {
        float pfv[2][8][4];
#pragma unroll
        for (int mi = 0; mi < 2; ++mi)
#pragma unroll
            for (int nj = 0; nj < 8; ++nj) {
                int cc = wn + nj*8 + 2*tg;
                pfv[mi][nj][0] = c[mi][nj][0] + __ldg(fb2+cc);
                pfv[mi][nj][1] = c[mi][nj][1] + __ldg(fb2+cc+1);
                pfv[mi][nj][2] = c[mi][nj][2] + __ldg(fb2+cc);
                pfv[mi][nj][3] = c[mi][nj][3] + __ldg(fb2+cc+1);
            }
        __syncthreads();
#pragma unroll
        for (int mi = 0; mi < 2; ++mi)
#pragma unroll
            for (int nj = 0; nj < 8; ++nj) {
                int rA = wm + mi*16 + g, cc = wn + nj*8 + 2*tg;
                H[rA*HP+cc]       = __uint_as_float(rna(pfv[mi][nj][0]));
                H[rA*HP+cc+1]     = __uint_as_float(rna(pfv[mi][nj][1]));
                H[(rA+8)*HP+cc]   = __uint_as_float(rna(pfv[mi][nj][2]));
                H[(rA+8)*HP+cc+1] = __uint_as_float(rna(pfv[mi][nj][3]));
            }
    }
    __syncthreads();

    // ---- layer 3 (seg inner) + fused seg head ----
    float acc[4][3];
#pragma unroll
    for (int ri = 0; ri < 4; ++ri)
#pragma unroll
        for (int cl = 0; cl < 3; ++cl) acc[ri][cl] = 0.f;

    for (int jh = 0; jh < 2; ++jh) {
#pragma unroll
        for (int mi = 0; mi < 2; ++mi)
#pragma unroll
            for (int nj = 0; nj < 8; ++nj)
#pragma unroll
                for (int q = 0; q < 4; ++q) c[mi][nj][q] = 0.f;
        for (int kc = 0; kc < 128; kc += 32) {
#pragma unroll
            for (int m = 0; m < 16; ++m) {
                int idx = m*256 + t, row = idx >> 5, kk = idx & 31;
                Bs[row*SP+kk] = __uint_as_float(
                    rna(gw1[(size_t)(jh*128+row)*DD + 128 + kc + kk]));
            }
            __syncthreads();
#pragma unroll
            for (int k0 = 0; k0 < 32; k0 += 8) {
                unsigned a[2][4], b[8][2];
#pragma unroll
                for (int mi = 0; mi < 2; ++mi) {
                    int rr = wm + mi*16 + g;
                    a[mi][0] = __float_as_uint(H[rr*HP + kc+k0+tg]);
                    a[mi][1] = __float_as_uint(H[(rr+8)*HP + kc+k0+tg]);
                    a[mi][2] = __float_as_uint(H[rr*HP + kc+k0+tg+4]);
                    a[mi][3] = __float_as_uint(H[(rr+8)*HP + kc+k0+tg+4]);
                }
#pragma unroll
                for (int nj = 0; nj < 8; ++nj) {
                    int nr = wn + nj*8 + g;
                    b[nj][0] = __float_as_uint(Bs[nr*SP + k0+tg]);
                    b[nj][1] = __float_as_uint(Bs[nr*SP + k0+tg+4]);
                }
#pragma unroll
                for (int mi = 0; mi < 2; ++mi)
#pragma unroll
                    for (int nj = 0; nj < 8; ++nj) mma_tf32(c[mi][nj], a[mi], b[nj]);
            }
            __syncthreads();
        }
        // accumulate 3-class GEMV partials for this jh's 128 columns
#pragma unroll
        for (int mi = 0; mi < 2; ++mi)
#pragma unroll
            for (int nj = 0; nj < 8; ++nj) {
                int cj = jh*128 + wn + nj*8 + 2*tg;
                float s0 = sslot[cj], s1v = sslot[cj+1];
                float v00 = fmaxf(c[mi][nj][0] + s0,  0.f);
                float v01 = fmaxf(c[mi][nj][1] + s1v, 0.f);
                float v10 = fmaxf(c[mi][nj][2] + s0,  0.f);
                float v11 = fmaxf(c[mi][nj][3] + s1v, 0.f);
#pragma unroll
                for (int cl = 0; cl < 3; ++cl) {
                    float wa = sgw2[cl*256 + cj], wb = sgw2[cl*256 + cj + 1];
                    acc[mi*2][cl]   += v00*wa + v01*wb;
                    acc[mi*2+1][cl] += v10*wa + v11*wb;
                }
            }
    }
    // reduce over the 4 tg lanes (same row, different columns)
#pragma unroll
    for (int ri = 0; ri < 4; ++ri)
#pragma unroll
        for (int cl = 0; cl < 3; ++cl) {
            float v = acc[ri][cl];
            v += __shfl_xor_sync(0xFFFFFFFFu, v, 1);
            v += __shfl_xor_sync(0xFFFFFFFFu, v, 2);
            acc[ri][cl] = v;
        }
    if (tg == 0) {
        int wi = w >> 2;
#pragma unroll
        for (int ri = 0; ri < 4; ++ri) {
            int row = wm + (ri >> 1)*16 + g + (ri & 1)*8;
#pragma unroll
            for (int cl = 0; cl < 3; ++cl)
                part[row*6 + wi*3 + cl] = acc[ri][cl];
        }
    }
    __syncthreads();
    if (t < 128) {
        int row = t, r = r0 + row, s = r & 255;
        float a0 = part[row*6+0] + part[row*6+3] + __ldg(gb2);
        float a1 = part[row*6+1] + part[row*6+4] + __ldg(gb2+1);
        float a2 = part[row*6+2] + part[row*6+5] + __ldg(gb2+2);
        float m = fmaxf(a0, fmaxf(a1, a2));
        float e0 = expf(a0 - m), e1 = expf(a1 - m), e2 = expf(a2 - m);
        float inv = 1.f / (e0 + e1 + e2);
        e0 *= inv; e1 *= inv; e2 *= inv;
        size_t pb = (size_t)65536 + 12582912 + ((size_t)s*256 + n)*3;
        out[pb] = e0; out[pb+1] = e1; out[pb+2] = e2;
        int i = g_feat_idx[r];
        size_t sb = (size_t)65536 + (size_t)n*49152 + i;
        out[sb] = e0; out[sb + 16384] = e1; out[sb + 32768] = e2;
    }
}

// ---------------------------------------------------------------------------
extern "C" void kernel_launch(void* const* d_in, const int* in_sizes, int n_in,
                              void* d_out, int out_size)
{
    const float* features = (const float*)d_in[0];
    const float* pos      = (const float*)d_in[1];
    const int*   bidx     = (const int*)d_in[2];
    const float* curio    = (const float*)d_in[3];
    const float* slots    = (const float*)d_in[5];
    const int*   cov_sel  = (const int*)d_in[6];
    const float* ipw = (const float*)d_in[7];
    const float* ipb = (const float*)d_in[8];
    const float* opw = (const float*)d_in[9];
    const float* opb = (const float*)d_in[10];
    const float* lng = (const float*)d_in[11];
    const float* lnb = (const float*)d_in[12];
    const float* sw1 = (const float*)d_in[13];
    const float* sb1 = (const float*)d_in[14];
    const float* sw2 = (const float*)d_in[15];
    const float* sb2 = (const float*)d_in[16];
    const float* fw1 = (const float*)d_in[17];
    const float* fb1 = (const float*)d_in[18];
    const float* fw2 = (const float*)d_in[19];
    const float* fb2 = (const float*)d_in[20];
    const float* gw1 = (const float*)d_in[21];
    const float* gb1 = (const float*)d_in[22];
    const float* gw2 = (const float*)d_in[23];
    const float* gb2 = (const float*)d_in[24];
    float* out = (float*)d_out;

    cudaFuncSetAttribute(k_sort, cudaFuncAttributeMaxDynamicSharedMemorySize,
                         (int)sizeof(SortSmem));
    cudaFuncSetAttribute(k_fused, cudaFuncAttributeMaxDynamicSharedMemorySize, FU_SMEM);

    cudaMemsetAsync(d_out, 0, (size_t)out_size * sizeof(float));
    // profiler captures launch index 4 (memset counts) -> k_gather this round
    k_sort<<<NQ, 512, sizeof(SortSmem)>>>(curio, cov_sel);
    k_nop<<<1, 1>>>();
    k_nop<<<1, 1>>>();
    k_gather<<<RTOT/8, 256>>>(features, pos, bidx);
    k_qprep<<<NQ, 256>>>(slots, ipw, ipb);
    dim3 glog(NQ, 4);
    k_logits<<<glog, 256, LG_SMEM>>>();
    k_soft<<<NQ, 256>>>();
    dim3 gg(NQ, 2);
    k_g<<<gg, 256>>>(features, bidx);
    k_slotpath<<<NQ, 256>>>(slots, ipw, ipb, opw, opb, lng, lnb,
                            sw1, sb1, sw2, sb2, gw1, gb1, out);
    k_fused<<<RTOT/128, 256, FU_SMEM>>>(fw1, fb1, fw2, fb2, gw1, gw2, gb2, out);
}

// round 14
// speedup vs baseline: 1.7281x; 1.0558x over previous
#include <cuda_runtime.h>
#include <cuda_bf16.h>
#include <cstdint>
#include <math.h>
#include <cub/block/block_radix_sort.cuh>

#define NQ 256
#define SSN 256
#define DD 256
#define HWT 16384
#define RTOT (NQ*SSN)

// ---------------- scratch (device globals; no allocation allowed) -----------
__device__ __align__(16) int   g_feat_idx[RTOT];
__device__ __align__(16) float g_keys[RTOT*DD];
__device__ __align__(16) float g_qw[NQ*8*DD];
__device__ __align__(16) float g_gp[2][NQ*8*DD];
__device__ __align__(16) float g_slotc[NQ*DD];
__device__ __align__(16) float g_lg[NQ*8*SSN];

// ---------------- tf32 mma helpers ------------------------------------------
__device__ __forceinline__ unsigned rna(float x) {
    unsigned o; asm("cvt.rna.tf32.f32 %0, %1;" : "=r"(o) : "f"(x)); return o;
}
__device__ __forceinline__ float rnaf(float x) {
    return __uint_as_float(rna(x));
}
__device__ __forceinline__ void mma_tf32(float* c, const unsigned* a, const unsigned* b) {
    asm volatile("mma.sync.aligned.m16n8k8.row.col.f32.tf32.tf32.f32 "
        "{%0,%1,%2,%3}, {%4,%5,%6,%7}, {%8,%9}, {%0,%1,%2,%3};"
        : "+f"(c[0]), "+f"(c[1]), "+f"(c[2]), "+f"(c[3])
        : "r"(a[0]), "r"(a[1]), "r"(a[2]), "r"(a[3]), "r"(b[0]), "r"(b[1]));
}

// ---------------- profiling alignment dummies --------------------------------
__global__ void k_nop() {}

// ---------------- 1) per-row stable descending argsort + rank select --------
// Stable radix SortDescending on mono(float) keys with u16 idx payload:
// ties keep input (idx-ascending) order == jnp.argsort(-x) exactly.
using Sorter = cub::BlockRadixSort<unsigned, 512, 32, unsigned short, 6>;
struct SortSmem { union { Sorter::TempStorage ts; unsigned short sidx[HWT]; }; };

__global__ void __launch_bounds__(512, 1)
k_sort(const float* __restrict__ curio, const int* __restrict__ cov_sel)
{
    extern __shared__ char raw[];
    SortSmem& sm = *reinterpret_cast<SortSmem*>(raw);
    const int n = blockIdx.x;
    const float* row = curio + (size_t)n * HWT;
    unsigned k[32]; unsigned short v[32];
    const int base = threadIdx.x * 32;
#pragma unroll
    for (int j = 0; j < 32; ++j) {
        unsigned u = __float_as_uint(row[base + j]);
        k[j] = u ^ (((unsigned)((int)u >> 31)) | 0x80000000u);
        v[j] = (unsigned short)(base + j);
    }
    Sorter(sm.ts).SortDescending(k, v, 0, 32);
    __syncthreads();
#pragma unroll
    for (int j = 0; j < 32; ++j) sm.sidx[base + j] = v[j];
    __syncthreads();
    if (threadIdx.x < SSN) {
        int s = threadIdx.x;
        int rank = (s < 192) ? s : 192 + cov_sel[s - 192];
        g_feat_idx[n * SSN + s] = (int)sm.sidx[rank];
    }
}

// ---------------- 2) gather keys = f + p (warp per row) ---------------------
__global__ void __launch_bounds__(256)
k_gather(const float* __restrict__ feat, const float* __restrict__ pos,
         const int* __restrict__ bidx)
{
    int w = threadIdx.x >> 5, l = threadIdx.x & 31;
    int r = blockIdx.x * 8 + w;
    int n = r >> 8;
    int i = g_feat_idx[r];
    int b = bidx[n];
    size_t src = ((size_t)i * 8 + b) * DD;
    size_t dst = (size_t)r * DD;
#pragma unroll
    for (int c = 0; c < 2; ++c) {
        int e = (l + c * 32) * 4;
        float4 fv = *(const float4*)(feat + src + e);
        float4 pv = *(const float4*)(pos + src + e);
        *(float4*)(g_keys + dst + e) =
            make_float4(fv.x + pv.x, fv.y + pv.y, fv.z + pv.z, fv.w + pv.w);
    }
}

// ---------------- 3) q, then qw = q@wk folded -------------------------------
__global__ void __launch_bounds__(256)
k_qprep(const float* __restrict__ slots, const float* __restrict__ ipw,
        const float* __restrict__ ipb)
{
    __shared__ float sl[DD], qs[DD];
    int n = blockIdx.x, t = threadIdx.x;
    sl[t] = slots[n * DD + t];
    __syncthreads();
    {
        const float* wr = ipw + (size_t)t * DD;
        float a = ipb[t];
#pragma unroll 8
        for (int e = 0; e < DD; e += 4) {
            float4 w4 = *(const float4*)(wr + e);
            a += w4.x*sl[e] + w4.y*sl[e+1] + w4.z*sl[e+2] + w4.w*sl[e+3];
        }
        qs[t] = a * 0.17677669529663687f;
    }
    __syncthreads();
    for (int h = 0; h < 8; ++h) {
        float a = 0.f;
#pragma unroll
        for (int d = 0; d < 32; ++d) {
            int hd = h * 32 + d;
            a += qs[hd] * __ldg(ipw + (size_t)(DD + hd) * DD + t);
        }
        g_qw[n * 2048 + h * DD + t] = a;
    }
}

// ---------------- 4a) logits: grid (NQ, 4) ----------------------------------
#define LG_SMEM ((8*260 + 32*260)*4)
__global__ void __launch_bounds__(256)
k_logits()
{
    extern __shared__ float sm[];
    float* qw_s = sm;
    float* ks   = sm + 8*260;
    const int n = blockIdx.x, q = blockIdx.y, t = threadIdx.x;
    for (int i = t; i < 2048; i += 256)
        qw_s[(i >> 8)*260 + (i & 255)] = g_qw[n*2048 + i];
    const int sl = t >> 3, h = t & 7;
#pragma unroll
    for (int c = 0; c < 2; ++c) {
        int s0 = q*64 + c*32;
        __syncthreads();
        for (int i = t; i < 32*64; i += 256) {
            int row = i >> 6, e4 = (i & 63)*4;
            *(float4*)(ks + row*260 + e4) =
                *(const float4*)(g_keys + ((size_t)(n*SSN + s0 + row))*DD + e4);
        }
        __syncthreads();
        float a = 0.f;
#pragma unroll 8
        for (int e = 0; e < DD; e += 4) {
            float4 kv = *(float4*)(ks + sl*260 + e);
            float4 qv = *(float4*)(qw_s + h*260 + e);
            a += kv.x*qv.x + kv.y*qv.y + kv.z*qv.z + kv.w*qv.w;
        }
        g_lg[n*2048 + h*SSN + s0 + sl] = a;
    }
}

// ---------------- 4b) softmax (recomputed per block) + G partials -----------
__global__ void __launch_bounds__(256)
k_g(const float* __restrict__ feat, const int* __restrict__ bidx)
{
    __shared__ float lg_s[2048];
    __shared__ float at[128*8];
    __shared__ int sidx[128];
    int n = blockIdx.x, half = blockIdx.y, t = threadIdx.x;
    int w = t >> 5, l = t & 31;
    for (int i = t; i < 2048; i += 256) lg_s[i] = g_lg[n*2048 + i];
    if (t < 128) sidx[t] = g_feat_idx[n*SSN + half*128 + t];
    __syncthreads();
    // full softmax over s for head w; keep weights for this block's half
    float lv[8]; float mx = -1e30f;
#pragma unroll
    for (int k = 0; k < 8; ++k) {
        lv[k] = lg_s[w*256 + l + k*32];
        mx = fmaxf(mx, lv[k]);
    }
#pragma unroll
    for (int o = 16; o > 0; o >>= 1) mx = fmaxf(mx, __shfl_xor_sync(0xFFFFFFFFu, mx, o));
    float sum = 0.f;
#pragma unroll
    for (int k = 0; k < 8; ++k) { lv[k] = expf(lv[k] - mx); sum += lv[k]; }
#pragma unroll
    for (int o = 16; o > 0; o >>= 1) sum += __shfl_xor_sync(0xFFFFFFFFu, sum, o);
    float inv = 1.f / sum;
#pragma unroll
    for (int k = 0; k < 8; ++k) {
        int s = l + k*32;
        if ((s >> 7) == half) at[(s - half*128)*8 + w] = lv[k] * inv;
    }
    __syncthreads();
    int b = bidx[n];
    float acc[8] = {0,0,0,0,0,0,0,0};
#pragma unroll 4
    for (int s = 0; s < 128; ++s) {
        float fv = feat[((size_t)sidx[s]*8 + b)*DD + t];
#pragma unroll
        for (int h = 0; h < 8; ++h) acc[h] += at[s*8 + h] * fv;
    }
#pragma unroll
    for (int h = 0; h < 8; ++h) g_gp[half][n*2048 + h*DD + t] = acc[h];
}

// ---------------- 5) slot path: o, delta, LN, slot-MLP, slotc ---------------
__global__ void __launch_bounds__(256)
k_slotpath(const float* __restrict__ slots, const float* __restrict__ ipw,
           const float* __restrict__ ipb, const float* __restrict__ opw,
           const float* __restrict__ opb, const float* __restrict__ lng,
           const float* __restrict__ lnb, const float* __restrict__ sw1,
           const float* __restrict__ sb1, const float* __restrict__ sw2,
           const float* __restrict__ sb2, const float* __restrict__ gw1,
           const float* __restrict__ gb1, float* __restrict__ out)
{
    __shared__ float G[2048], ov[256], so[256], hid[128], ps[128], red[8];
    int n = blockIdx.x, t = threadIdx.x;
    for (int i = t; i < 2048; i += 256)
        G[i] = g_gp[0][n*2048 + i] + g_gp[1][n*2048 + i];
    __syncthreads();
    {
        int h = t >> 5;
        const float* wr = ipw + (size_t)(512 + t) * DD;
        float a = ipb[512 + t];
#pragma unroll 8
        for (int e = 0; e < DD; e += 4) {
            float4 w4 = *(const float4*)(wr + e);
            a += w4.x*G[h*256+e] + w4.y*G[h*256+e+1] + w4.z*G[h*256+e+2] + w4.w*G[h*256+e+3];
        }
        ov[t] = a;
    }
    __syncthreads();
    float x;
    {
        const float* wr = opw + (size_t)t * DD;
        float a = opb[t];
#pragma unroll 8
        for (int e = 0; e < DD; e += 4) {
            float4 w4 = *(const float4*)(wr + e);
            a += w4.x*ov[e] + w4.y*ov[e+1] + w4.z*ov[e+2] + w4.w*ov[e+3];
        }
        x = slots[n*DD + t] + a;
    }
    float v = x;
#pragma unroll
    for (int o = 16; o > 0; o >>= 1) v += __shfl_xor_sync(0xFFFFFFFFu, v, o);
    if ((t & 31) == 0) red[t >> 5] = v;
    __syncthreads();
    float mu = 0.f;
#pragma unroll
    for (int i = 0; i < 8; ++i) mu += red[i];
    mu *= (1.f/256.f);
    __syncthreads();
    float d = x - mu; v = d * d;
#pragma unroll
    for (int o = 16; o > 0; o >>= 1) v += __shfl_xor_sync(0xFFFFFFFFu, v, o);
    if ((t & 31) == 0) red[t >> 5] = v;
    __syncthreads();
    float var = 0.f;
#pragma unroll
    for (int i = 0; i < 8; ++i) var += red[i];
    var *= (1.f/256.f);
    float sov = d * rsqrtf(var + 1e-5f) * lng[t] + lnb[t];
    so[t] = sov;
    out[n*DD + t] = sov;
    __syncthreads();
    if (t < 128) {
        const float* wr = sw1 + (size_t)t * DD;
        float a = sb1[t];
#pragma unroll 8
        for (int e = 0; e < DD; e += 4) {
            float4 w4 = *(const float4*)(wr + e);
            a += w4.x*so[e] + w4.y*so[e+1] + w4.z*so[e+2] + w4.w*so[e+3];
        }
        hid[t] = fmaxf(a, 0.f);
    }
    __syncthreads();
    if (t < 128) {
        const float* wr = sw2 + (size_t)t * 128;
        float a = sb2[t];
#pragma unroll 8
        for (int e = 0; e < 128; e += 4) {
            float4 w4 = *(const float4*)(wr + e);
            a += w4.x*hid[e] + w4.y*hid[e+1] + w4.z*hid[e+2] + w4.w*hid[e+3];
        }
        ps[t] = a;
    }
    __syncthreads();
    {
        const float* wr = gw1 + (size_t)t * DD;
        float a = gb1[t];
#pragma unroll 8
        for (int i = 0; i < 128; i += 4) {
            float4 w4 = *(const float4*)(wr + i);
            a += w4.x*ps[i] + w4.y*ps[i+1] + w4.z*ps[i+2] + w4.w*ps[i+3];
        }
        g_slotc[n*DD + t] = a;
    }
}

// ---------------- 6) fused featMLP(L1,L2) + seg GEMM + seg head, 64-row tiles
// 8 warps in 2(m) x 4(n) layout; warp tile 32x32. 68.6KB smem -> 3 CTAs/SM.
#define HP 132
#define SP 36
#define FU_FLOATS (64*HP + 64*SP + 128*SP + 256 + 768 + 64*12)
#define FU_SMEM (FU_FLOATS*4)

__global__ void __launch_bounds__(256, 2)
k_fused(const float* __restrict__ fw1, const float* __restrict__ fb1,
        const float* __restrict__ fw2, const float* __restrict__ fb2,
        const float* __restrict__ gw1, const float* __restrict__ gw2,
        const float* __restrict__ gb2, float* __restrict__ out)
{
    extern __shared__ float sm[];
    float* H     = sm;                      // 64 x HP (layer1 out, then pf)
    float* As    = sm + 64*HP;              // 64 x SP
    float* Bs    = As + 64*SP;              // 128 x SP
    float* sslot = Bs + 128*SP;             // 256 (slotc row for this n)
    float* sgw2  = sslot + 256;             // 3 x 256
    float* part  = sgw2 + 768;              // 64 x 4 x 3
    const int t = threadIdx.x, lane = t & 31, w = t >> 5;
    const int r0 = blockIdx.x * 64, n = blockIdx.x >> 2;
    const int wm = (w & 1) * 32, wn = (w >> 1) * 32;
    const int g = lane >> 2, tg = lane & 3;

    sslot[t] = g_slotc[n*DD + t];
    for (int i = t; i < 768; i += 256) sgw2[i] = __ldg(gw2 + i);

    float c[2][4][4];
#pragma unroll
    for (int mi = 0; mi < 2; ++mi)
#pragma unroll
        for (int nj = 0; nj < 4; ++nj)
#pragma unroll
            for (int q = 0; q < 4; ++q) c[mi][nj][q] = 0.f;

    // ---- layer 1: H = relu(keys @ fw1^T + fb1), K=256 ----
    for (int kc = 0; kc < 256; kc += 32) {
#pragma unroll
        for (int m = 0; m < 8; ++m) {
            int idx = m*256 + t, row = idx >> 5, kk = idx & 31;
            As[row*SP+kk] = rnaf(g_keys[(size_t)(r0+row)*DD + kc + kk]);
        }
#pragma unroll
        for (int m = 0; m < 16; ++m) {
            int idx = m*256 + t, row = idx >> 5, kk = idx & 31;
            Bs[row*SP+kk] = rnaf(fw1[(size_t)row*DD + kc + kk]);
        }
        __syncthreads();
#pragma unroll
        for (int k0 = 0; k0 < 32; k0 += 8) {
            unsigned a[2][4], b[4][2];
#pragma unroll
            for (int mi = 0; mi < 2; ++mi) {
                int rr = wm + mi*16 + g;
                a[mi][0] = __float_as_uint(As[rr*SP + k0+tg]);
                a[mi][1] = __float_as_uint(As[(rr+8)*SP + k0+tg]);
                a[mi][2] = __float_as_uint(As[rr*SP + k0+tg+4]);
                a[mi][3] = __float_as_uint(As[(rr+8)*SP + k0+tg+4]);
            }
#pragma unroll
            for (int nj = 0; nj < 4; ++nj) {
                int nr = wn + nj*8 + g;
                b[nj][0] = __float_as_uint(Bs[nr*SP + k0+tg]);
                b[nj][1] = __float_as_uint(Bs[nr*SP + k0+tg+4]);
            }
#pragma unroll
            for (int mi = 0; mi < 2; ++mi)
#pragma unroll
                for (int nj = 0; nj < 4; ++nj) mma_tf32(c[mi][nj], a[mi], b[nj]);
        }
        __syncthreads();
    }
#pragma unroll
    for (int mi = 0; mi < 2; ++mi)
#pragma unroll
        for (int nj = 0; nj < 4; ++nj) {
            int rA = wm + mi*16 + g, cc = wn + nj*8 + 2*tg;
            H[rA*HP+cc]       = rnaf(fmaxf(c[mi][nj][0] + __ldg(fb1+cc),   0.f));
            H[rA*HP+cc+1]     = rnaf(fmaxf(c[mi][nj][1] + __ldg(fb1+cc+1), 0.f));
            H[(rA+8)*HP+cc]   = rnaf(fmaxf(c[mi][nj][2] + __ldg(fb1+cc),   0.f));
            H[(rA+8)*HP+cc+1] = rnaf(fmaxf(c[mi][nj][3] + __ldg(fb1+cc+1), 0.f));
#pragma unroll
            for (int q = 0; q < 4; ++q) c[mi][nj][q] = 0.f;
        }
    __syncthreads();

    // ---- layer 2: pf = H @ fw2^T + fb2, K=128, A = H (in smem) ----
    for (int kc = 0; kc < 128; kc += 32) {
#pragma unroll
        for (int m = 0; m < 16; ++m) {
            int idx = m*256 + t, row = idx >> 5, kk = idx & 31;
            Bs[row*SP+kk] = rnaf(fw2[(size_t)row*128 + kc + kk]);
        }
        __syncthreads();
#pragma unroll
        for (int k0 = 0; k0 < 32; k0 += 8) {
            unsigned a[2][4], b[4][2];
#pragma unroll
            for (int mi = 0; mi < 2; ++mi) {
                int rr = wm + mi*16 + g;
                a[mi][0] = __float_as_uint(H[rr*HP + kc+k0+tg]);
                a[mi][1] = __float_as_uint(H[(rr+8)*HP + kc+k0+tg]);
                a[mi][2] = __float_as_uint(H[rr*HP + kc+k0+tg+4]);
                a[mi][3] = __float_as_uint(H[(rr+8)*HP + kc+k0+tg+4]);
            }
#pragma unroll
            for (int nj = 0; nj < 4; ++nj) {
                int nr = wn + nj*8 + g;
                b[nj][0] = __float_as_uint(Bs[nr*SP + k0+tg]);
                b[nj][1] = __float_as_uint(Bs[nr*SP + k0+tg+4]);
            }
#pragma unroll
            for (int mi = 0; mi < 2; ++mi)
#pragma unroll
                for (int nj = 0; nj < 4; ++nj) mma_tf32(c[mi][nj], a[mi], b[nj]);
        }
        __syncthreads();
    }
    // overwrite H with tf32-rounded pf (all reads done: loop ends with sync)
    {
        float pfv[2][4][4];
#pragma unroll
        for (int mi = 0; mi < 2; ++mi)
#pragma unroll
            for (int nj = 0; nj < 4; ++nj) {
                int cc = wn + nj*8 + 2*tg;
                pfv[mi][nj][0] = c[mi][nj][0] + __ldg(fb2+cc);
                pfv[mi][nj][1] = c[mi][nj][1] + __ldg(fb2+cc+1);
                pfv[mi][nj][2] = c[mi][nj][2] + __ldg(fb2+cc);
                pfv[mi][nj][3] = c[mi][nj][3] + __ldg(fb2+cc+1);
            }
        __syncthreads();
#pragma unroll
        for (int mi = 0; mi < 2; ++mi)
#pragma unroll
            for (int nj = 0; nj < 4; ++nj) {
                int rA = wm + mi*16 + g, cc = wn + nj*8 + 2*tg;
                H[rA*HP+cc]       = rnaf(pfv[mi][nj][0]);
                H[rA*HP+cc+1]     = rnaf(pfv[mi][nj][1]);
                H[(rA+8)*HP+cc]   = rnaf(pfv[mi][nj][2]);
                H[(rA+8)*HP+cc+1] = rnaf(pfv[mi][nj][3]);
            }
    }
    __syncthreads();

    // ---- layer 3 (seg inner) + fused seg head ----
    float acc[4][3];
#pragma unroll
    for (int ri = 0; ri < 4; ++ri)
#pragma unroll
        for (int cl = 0; cl < 3; ++cl) acc[ri][cl] = 0.f;

    for (int jh = 0; jh < 2; ++jh) {
#pragma unroll
        for (int mi = 0; mi < 2; ++mi)
#pragma unroll
            for (int nj = 0; nj < 4; ++nj)
#pragma unroll
                for (int q = 0; q < 4; ++q) c[mi][nj][q] = 0.f;
        for (int kc = 0; kc < 128; kc += 32) {
#pragma unroll
            for (int m = 0; m < 16; ++m) {
                int idx = m*256 + t, row = idx >> 5, kk = idx & 31;
                Bs[row*SP+kk] = rnaf(gw1[(size_t)(jh*128+row)*DD + 128 + kc + kk]);
            }
            __syncthreads();
#pragma unroll
            for (int k0 = 0; k0 < 32; k0 += 8) {
                unsigned a[2][4], b[4][2];
#pragma unroll
                for (int mi = 0; mi < 2; ++mi) {
                    int rr = wm + mi*16 + g;
                    a[mi][0] = __float_as_uint(H[rr*HP + kc+k0+tg]);
                    a[mi][1] = __float_as_uint(H[(rr+8)*HP + kc+k0+tg]);
                    a[mi][2] = __float_as_uint(H[rr*HP + kc+k0+tg+4]);
                    a[mi][3] = __float_as_uint(H[(rr+8)*HP + kc+k0+tg+4]);
                }
#pragma unroll
                for (int nj = 0; nj < 4; ++nj) {
                    int nr = wn + nj*8 + g;
                    b[nj][0] = __float_as_uint(Bs[nr*SP + k0+tg]);
                    b[nj][1] = __float_as_uint(Bs[nr*SP + k0+tg+4]);
                }
#pragma unroll
                for (int mi = 0; mi < 2; ++mi)
#pragma unroll
                    for (int nj = 0; nj < 4; ++nj) mma_tf32(c[mi][nj], a[mi], b[nj]);
            }
            __syncthreads();
        }
        // accumulate 3-class GEMV partials for this jh's 128 columns
#pragma unroll
        for (int mi = 0; mi < 2; ++mi)
#pragma unroll
            for (int nj = 0; nj < 4; ++nj) {
                int cj = jh*128 + wn + nj*8 + 2*tg;
                float s0 = sslot[cj], s1v = sslot[cj+1];
                float v00 = fmaxf(c[mi][nj][0] + s0,  0.f);
                float v01 = fmaxf(c[mi][nj][1] + s1v, 0.f);
                float v10 = fmaxf(c[mi][nj][2] + s0,  0.f);
                float v11 = fmaxf(c[mi][nj][3] + s1v, 0.f);
#pragma unroll
                for (int cl = 0; cl < 3; ++cl) {
                    float wa = sgw2[cl*256 + cj], wb = sgw2[cl*256 + cj + 1];
                    acc[mi*2][cl]   += v00*wa + v01*wb;
                    acc[mi*2+1][cl] += v10*wa + v11*wb;
                }
            }
    }
    // reduce over the 4 tg lanes (same row, different columns)
#pragma unroll
    for (int ri = 0; ri < 4; ++ri)
#pragma unroll
        for (int cl = 0; cl < 3; ++cl) {
            float v = acc[ri][cl];
            v += __shfl_xor_sync(0xFFFFFFFFu, v, 1);
            v += __shfl_xor_sync(0xFFFFFFFFu, v, 2);
            acc[ri][cl] = v;
        }
    if (tg == 0) {
        int wi = w >> 1;  // n-warp index 0..3
#pragma unroll
        for (int ri = 0; ri < 4; ++ri) {
            int row = wm + (ri >> 1)*16 + g + (ri & 1)*8;
#pragma unroll
            for (int cl = 0; cl < 3; ++cl)
                part[row*12 + wi*3 + cl] = acc[ri][cl];
        }
    }
    __syncthreads();
    if (t < 64) {
        int row = t, r = r0 + row, s = r & 255;
        float a0 = part[row*12+0] + part[row*12+3] + part[row*12+6] + part[row*12+9]  + __ldg(gb2);
        float a1 = part[row*12+1] + part[row*12+4] + part[row*12+7] + part[row*12+10] + __ldg(gb2+1);
        float a2 = part[row*12+2] + part[row*12+5] + part[row*12+8] + part[row*12+11] + __ldg(gb2+2);
        float m = fmaxf(a0, fmaxf(a1, a2));
        float e0 = expf(a0 - m), e1 = expf(a1 - m), e2 = expf(a2 - m);
        float inv = 1.f / (e0 + e1 + e2);
        e0 *= inv; e1 *= inv; e2 *= inv;
        size_t pb = (size_t)65536 + 12582912 + ((size_t)s*256 + n)*3;
        out[pb] = e0; out[pb+1] = e1; out[pb+2] = e2;
        int i = g_feat_idx[r];
        size_t sb = (size_t)65536 + (size_t)n*49152 + i;
        out[sb] = e0; out[sb + 16384] = e1; out[sb + 32768] = e2;
    }
}

// ---------------------------------------------------------------------------
extern "C" void kernel_launch(void* const* d_in, const int* in_sizes, int n_in,
                              void* d_out, int out_size)
{
    const float* features = (const float*)d_in[0];
    const float* pos      = (const float*)d_in[1];
    const int*   bidx     = (const int*)d_in[2];
    const float* curio    = (const float*)d_in[3];
    const float* slots    = (const float*)d_in[5];
    const int*   cov_sel  = (const int*)d_in[6];
    const float* ipw = (const float*)d_in[7];
    const float* ipb = (const float*)d_in[8];
    const float* opw = (const float*)d_in[9];
    const float* opb = (const float*)d_in[10];
    const float* lng = (const float*)d_in[11];
    const float* lnb = (const float*)d_in[12];
    const float* sw1 = (const float*)d_in[13];
    const float* sb1 = (const float*)d_in[14];
    const float* sw2 = (const float*)d_in[15];
    const float* sb2 = (const float*)d_in[16];
    const float* fw1 = (const float*)d_in[17];
    const float* fb1 = (const float*)d_in[18];
    const float* fw2 = (const float*)d_in[19];
    const float* fb2 = (const float*)d_in[20];
    const float* gw1 = (const float*)d_in[21];
    const float* gb1 = (const float*)d_in[22];
    const float* gw2 = (const float*)d_in[23];
    const float* gb2 = (const float*)d_in[24];
    float* out = (float*)d_out;

    cudaFuncSetAttribute(k_sort, cudaFuncAttributeMaxDynamicSharedMemorySize,
                         (int)sizeof(SortSmem));
    cudaFuncSetAttribute(k_fused, cudaFuncAttributeMaxDynamicSharedMemorySize, FU_SMEM);

    cudaMemsetAsync(d_out, 0, (size_t)out_size * sizeof(float));
    // profiler captures the 5th launch (memset counts) -> k_sort (RADIX_BITS=6)
    k_nop<<<1, 1>>>();
    k_nop<<<1, 1>>>();
    k_nop<<<1, 1>>>();
    k_sort<<<NQ, 512, sizeof(SortSmem)>>>(curio, cov_sel);
    k_gather<<<RTOT/8, 256>>>(features, pos, bidx);
    k_qprep<<<NQ, 256>>>(slots, ipw, ipb);
    dim3 glog(NQ, 4);
    k_logits<<<glog, 256, LG_SMEM>>>();
    dim3 gg(NQ, 2);
    k_g<<<gg, 256>>>(features, bidx);
    k_slotpath<<<NQ, 256>>>(slots, ipw, ipb, opw, opb, lng, lnb,
                            sw1, sb1, sw2, sb2, gw1, gb1, out);
    k_fused<<<RTOT/64, 256, FU_SMEM>>>(fw1, fb1, fw2, fb2, gw1, gw2, gb2, out);
}